// round 12
// baseline (speedup 1.0000x reference)
#include <cuda_runtime.h>
#include <cuda_fp16.h>
#include <math.h>

#define Bn 64
#define Tn 512
#define Cn 384
#define Hn 6
#define HDn 64
#define FFn 1536
#define BTn (Bn*Tn)
#define EPSn 1e-5f

#define SWS 20    // gemm smem row stride (u32 words)

// fp16 attention smem (u32 word strides)
#define STKW 36
#define STVW 20
#define BKS0 0
#define BVS0 (32*STKW)
#define BKS1 (BVS0 + 64*STVW)
#define BVS1 (BKS1 + 32*STKW)
#define BTOT (BVS1 + 64*STVW)

// ---------------- scratch ----------------
__device__ __half g_wqkv1[3*Cn*Cn];
__device__ __half g_wqkv2[3*Cn*Cn];
__device__ __half g_wp1[Cn*Cn];
__device__ __half g_wp2[Cn*Cn];
__device__ __half g_wf1t[FFn*Cn];
__device__ __half g_wf2t[Cn*FFn];
__device__ float  g_bqkv1[3*Cn];
__device__ float  g_bqkv2[3*Cn];
__device__ __half g_x16[(size_t)BTn*Cn];
__device__ __half g_o16[(size_t)BTn*Cn];
__device__ __half g_r16[(size_t)BTn*Cn];
__device__ __half g_h16[(size_t)BTn*FFn];
__device__ __half g_q16[(size_t)Bn*Hn*Tn*HDn];
__device__ __half g_k16[(size_t)Bn*Hn*Tn*HDn];
__device__ __half g_v16t[(size_t)Bn*Hn*HDn*Tn];
__device__ float g_p[(size_t)BTn*Cn];
__device__ float g_r1[(size_t)BTn*Cn];
__device__ float g_r2[(size_t)BTn*Cn];

// ---------------- fused prep ----------------
#define SEG0 (BTn*Cn)
#define SEG1 (3*Cn*Cn)
#define SEG2 (3*Cn*Cn)
#define SEG3 (Cn*Cn)
#define SEG4 (Cn*Cn)
#define SEG5 (FFn*Cn)
#define SEG6 (Cn*FFn)
#define SEG7 (3*Cn)
#define SEG8 (3*Cn)
#define PTOT (SEG0+SEG1+SEG2+SEG3+SEG4+SEG5+SEG6+SEG7+SEG8)

__device__ __forceinline__ void pack_qkv_w(const float* qw, const float* kw,
                                           const float* vw, __half* o, int i) {
    int n = i / Cn, k = i % Cn;
    int mat = n / Cn, local = n % Cn;
    int h = local >> 6, d = local & 63;
    const float* w = (mat == 0) ? qw : (mat == 1) ? kw : vw;
    o[i] = __float2half(w[((size_t)h * Cn + k) * HDn + d]);
}
__device__ __forceinline__ void pack_wt(const float* w, __half* o, int N, int K, int i) {
    int n = i / K, k = i % K;
    o[i] = __float2half(w[(size_t)k * N + n]);
}

__global__ void prep_all(
    const float* __restrict__ x, __half* __restrict__ x16,
    const float* __restrict__ q1w, const float* __restrict__ k1w, const float* __restrict__ v1w,
    __half* __restrict__ wqkv1,
    const float* __restrict__ q2w, const float* __restrict__ k2w, const float* __restrict__ v2w,
    __half* __restrict__ wqkv2,
    const float* __restrict__ p1w, __half* __restrict__ wp1,
    const float* __restrict__ p2w, __half* __restrict__ wp2,
    const float* __restrict__ f1w, __half* __restrict__ wf1,
    const float* __restrict__ f2w, __half* __restrict__ wf2,
    const float* __restrict__ q1b, const float* __restrict__ k1b, const float* __restrict__ v1b,
    float* __restrict__ bqkv1,
    const float* __restrict__ q2b, const float* __restrict__ k2b, const float* __restrict__ v2b,
    float* __restrict__ bqkv2)
{
    int i = blockIdx.x * blockDim.x + threadIdx.x;
    if (i >= PTOT) return;
    if (i < SEG0) { x16[i] = __float2half(x[i]); return; }
    i -= SEG0;
    if (i < SEG1) { pack_qkv_w(q1w, k1w, v1w, wqkv1, i); return; }
    i -= SEG1;
    if (i < SEG2) { pack_qkv_w(q2w, k2w, v2w, wqkv2, i); return; }
    i -= SEG2;
    if (i < SEG3) { pack_wt(p1w, wp1, Cn, Cn, i); return; }
    i -= SEG3;
    if (i < SEG4) { pack_wt(p2w, wp2, Cn, Cn, i); return; }
    i -= SEG4;
    if (i < SEG5) { pack_wt(f1w, wf1, FFn, Cn, i); return; }
    i -= SEG5;
    if (i < SEG6) { pack_wt(f2w, wf2, Cn, FFn, i); return; }
    i -= SEG6;
    if (i < SEG7) {
        const float* b = (i < Cn) ? q1b : (i < 2 * Cn) ? k1b : v1b;
        bqkv1[i] = b[i % Cn]; return;
    }
    i -= SEG7;
    {
        const float* b = (i < Cn) ? q2b : (i < 2 * Cn) ? k2b : v2b;
        bqkv2[i] = b[i % Cn];
    }
}

// ---------------- mma / ldmatrix / async helpers ----------------
__device__ __forceinline__ void mma16(float* d, const unsigned* a, const unsigned* b) {
    asm("mma.sync.aligned.m16n8k16.row.col.f32.f16.f16.f32 "
        "{%0,%1,%2,%3},{%4,%5,%6,%7},{%8,%9},{%0,%1,%2,%3};"
        : "+f"(d[0]), "+f"(d[1]), "+f"(d[2]), "+f"(d[3])
        : "r"(a[0]), "r"(a[1]), "r"(a[2]), "r"(a[3]), "r"(b[0]), "r"(b[1]));
}
__device__ __forceinline__ void ldsm4(unsigned* r, unsigned addr) {
    asm volatile("ldmatrix.sync.aligned.m8n8.x4.shared.b16 {%0,%1,%2,%3}, [%4];"
        : "=r"(r[0]), "=r"(r[1]), "=r"(r[2]), "=r"(r[3]) : "r"(addr));
}
__device__ __forceinline__ void ldsm2(unsigned* r, unsigned addr) {
    asm volatile("ldmatrix.sync.aligned.m8n8.x2.shared.b16 {%0,%1}, [%2];"
        : "=r"(r[0]), "=r"(r[1]) : "r"(addr));
}
__device__ __forceinline__ unsigned h2u(float a, float b) {
    __half2 h = __floats2half2_rn(a, b);
    return *(unsigned*)&h;
}
__device__ __forceinline__ void cp_async16(void* smem_dst, const void* gsrc) {
    unsigned saddr = (unsigned)__cvta_generic_to_shared(smem_dst);
    asm volatile("cp.async.ca.shared.global [%0], [%1], 16;\n" :: "r"(saddr), "l"(gsrc));
}
#define CP_COMMIT() asm volatile("cp.async.commit_group;\n" ::: "memory")
#define CP_WAIT1()  asm volatile("cp.async.wait_group 1;\n" ::: "memory")
#define CP_WAIT0()  asm volatile("cp.async.wait_group 0;\n" ::: "memory")

// ---------------- fp16 GEMM: 3-stage pipeline, 3 CTAs/SM, register-lean loop ------
// flags: 0 = fp32 out; 1 = relu + fp16 out; 2 = qkv scatter fp16 (+rope, q scaled)
__global__ __launch_bounds__(256, 3) void gemm_f16(
    const __half* __restrict__ A, const __half* __restrict__ Bm,
    const float* __restrict__ bias, float* __restrict__ Cout,
    __half* __restrict__ Cout16,
    int M, int N, int K, int flags,
    __half* __restrict__ oq, __half* __restrict__ ok, __half* __restrict__ ov)
{
    __shared__ __align__(16) unsigned As[3][128 * SWS];
    __shared__ __align__(16) unsigned Bs[3][128 * SWS];

    const int tid = threadIdx.x;
    const int lane = tid & 31, warp = tid >> 5;
    const int warpM = warp >> 2, warpN = warp & 3;
    const int bm = blockIdx.y * 128, bn = blockIdx.x * 128;
    const int qq = lane & 3, gg = lane >> 2;

    const int sRow = tid >> 1;
    const int sOff = (tid & 1) * 8;
    const __half* Ap = A + (size_t)(bm + sRow) * K + (tid & 1) * 16;
    const __half* Bp = Bm + (size_t)(bn + sRow) * K + (tid & 1) * 16;

    const int arS = warpM * 64 + (lane & 7) + ((lane >> 3) & 1) * 8;
    const int acS = (lane >> 4) * 4;
    const int brS = warpN * 32 + (lane & 7);
    const int bcS = ((lane >> 3) & 1) * 4;

    float acc[4][4][4];
#pragma unroll
    for (int i = 0; i < 4; i++)
#pragma unroll
        for (int j = 0; j < 4; j++)
#pragma unroll
            for (int r = 0; r < 4; r++) acc[i][j][r] = 0.f;

    const int KT = K >> 5;

    {
        unsigned* as = As[0]; unsigned* bs = Bs[0];
        cp_async16(as + sRow * SWS + sOff,     Ap);
        cp_async16(as + sRow * SWS + sOff + 4, Ap + 8);
        cp_async16(bs + sRow * SWS + sOff,     Bp);
        cp_async16(bs + sRow * SWS + sOff + 4, Bp + 8);
    }
    CP_COMMIT();
    {
        unsigned* as = As[1]; unsigned* bs = Bs[1];
        cp_async16(as + sRow * SWS + sOff,     Ap + 32);
        cp_async16(as + sRow * SWS + sOff + 4, Ap + 40);
        cp_async16(bs + sRow * SWS + sOff,     Bp + 32);
        cp_async16(bs + sRow * SWS + sOff + 4, Bp + 40);
    }
    CP_COMMIT();

    for (int kt = 0; kt < KT; kt++) {
        CP_WAIT1();
        __syncthreads();

        if (kt + 2 < KT) {
            int st = kt + 2; st -= (st >= 3) ? 3 : 0; st -= (st >= 3) ? 3 : 0;
            // simpler: (kt+2)%3 via conditional
            st = (kt + 2) % 3;
            unsigned* as = As[st]; unsigned* bs = Bs[st];
            const __half* ap = Ap + (size_t)(kt + 2) * 32;
            const __half* bp = Bp + (size_t)(kt + 2) * 32;
            cp_async16(as + sRow * SWS + sOff,     ap);
            cp_async16(as + sRow * SWS + sOff + 4, ap + 8);
            cp_async16(bs + sRow * SWS + sOff,     bp);
            cp_async16(bs + sRow * SWS + sOff + 4, bp + 8);
        }
        CP_COMMIT();

        const int st = kt % 3;
        const unsigned ab = (unsigned)__cvta_generic_to_shared(As[st]);
        const unsigned bb = (unsigned)__cvta_generic_to_shared(Bs[st]);
#pragma unroll
        for (int ko = 0; ko < 16; ko += 8) {
            unsigned bf[4][2];
#pragma unroll
            for (int ni = 0; ni < 4; ni++)
                ldsm2(bf[ni], bb + (((ni * 8 + brS) * SWS + ko + bcS) << 2));
#pragma unroll
            for (int mi = 0; mi < 4; mi++) {
                unsigned af[4];
                ldsm4(af, ab + (((mi * 16 + arS) * SWS + ko + acS) << 2));
#pragma unroll
                for (int ni = 0; ni < 4; ni++)
                    mma16(acc[mi][ni], af, bf[ni]);
            }
        }
    }

    const float scale = 0.051031036307982884f;   // 1/sqrt(384)
#pragma unroll
    for (int mi = 0; mi < 4; mi++) {
        int row0 = bm + warpM * 64 + mi * 16 + gg;
        float sn[2], cs[2];
        if (flags == 2) {
            sincosf((float)(row0 & 511), &sn[0], &cs[0]);
            sincosf((float)((row0 + 8) & 511), &sn[1], &cs[1]);
        }
#pragma unroll
        for (int ni = 0; ni < 4; ni++) {
            int col = bn + warpN * 32 + ni * 8 + qq * 2;
            float b0 = bias[col], b1 = bias[col + 1];
#pragma unroll
            for (int half = 0; half < 2; half++) {
                int row = row0 + half * 8;
                float xr = acc[mi][ni][half * 2 + 0] + b0;
                float xi = acc[mi][ni][half * 2 + 1] + b1;
                if (flags == 2) {
                    int mat = col / Cn;
                    if (mat < 2) {
                        float nr = cs[half] * xr - sn[half] * xi;
                        float ni2 = sn[half] * xr + cs[half] * xi;
                        xr = nr; xi = ni2;
                    }
                    int local = col - mat * Cn;
                    int h = local >> 6, d = local & 63;
                    int bbv = row >> 9, t = row & 511;
                    if (mat == 0) {
                        __half2 hv = __floats2half2_rn(xr * scale, xi * scale);
                        *(__half2*)(oq + ((size_t)(bbv * Hn + h) * Tn + t) * HDn + d) = hv;
                    } else if (mat == 1) {
                        __half2 hv = __floats2half2_rn(xr, xi);
                        *(__half2*)(ok + ((size_t)(bbv * Hn + h) * Tn + t) * HDn + d) = hv;
                    } else {
                        size_t vb = ((size_t)(bbv * Hn + h) * HDn + d) * Tn + t;
                        ov[vb]      = __float2half(xr);
                        ov[vb + Tn] = __float2half(xi);
                    }
                } else if (flags == 1) {
                    xr = fmaxf(xr, 0.f); xi = fmaxf(xi, 0.f);
                    __half2* p = (__half2*)(Cout16 + (size_t)row * N + col);
                    *p = __floats2half2_rn(xr, xi);
                } else {
                    float2* p = (float2*)(Cout + (size_t)row * N + col);
                    *p = make_float2(xr, xi);
                }
            }
        }
    }
}

// ---------------- fp16 causal flash attention: 128-query tile (unchanged R10) -----
__global__ __launch_bounds__(256) void attn_mma(
    const __half* __restrict__ q, const __half* __restrict__ k,
    const __half* __restrict__ v, __half* __restrict__ o)
{
    __shared__ __align__(16) unsigned sm[BTOT];

    const int bh = blockIdx.y;
    const int qt = gridDim.x - 1 - blockIdx.x;
    const int tid = threadIdx.x;
    const int warp = tid >> 5, lane = tid & 31;
    const int gg = lane >> 2, qq = lane & 3;
    const size_t base = (size_t)bh * Tn * HDn;
    const int q0 = qt * 128;
    const int ktiles = 4 * qt + 4;

    const int lrS = lane & 7;
    const int lcS = ((lane >> 3) & 1) * 4;

    {
        unsigned* kd = sm + BKS0;
        unsigned* vd = sm + BVS0;
        int r = tid >> 3, seg = tid & 7;
        cp_async16(kd + r * STKW + seg * 4, k + base + (size_t)r * 64 + seg * 8);
        int rv = tid >> 2, sv = tid & 3;
        cp_async16(vd + rv * STVW + sv * 4, v + base + (size_t)rv * Tn + sv * 8);
        CP_COMMIT();
    }

    unsigned qf[4][4];
    {
        const __half* q0p = q + base + (size_t)(q0 + warp * 16 + gg) * 64;
        const __half* q1p = q0p + 8 * 64;
#pragma unroll
        for (int ks = 0; ks < 4; ks++) {
            qf[ks][0] = *(const unsigned*)(q0p + ks * 16 + 2 * qq);
            qf[ks][1] = *(const unsigned*)(q1p + ks * 16 + 2 * qq);
            qf[ks][2] = *(const unsigned*)(q0p + ks * 16 + 2 * qq + 8);
            qf[ks][3] = *(const unsigned*)(q1p + ks * 16 + 2 * qq + 8);
        }
    }
    CP_WAIT0();
    __syncthreads();

    float oacc[8][4];
#pragma unroll
    for (int i = 0; i < 8; i++)
#pragma unroll
        for (int r = 0; r < 4; r++) oacc[i][r] = 0.f;
    float m0 = -INFINITY, m1 = -INFINITY, l0 = 0.f, l1 = 0.f;

    const int row0g = q0 + warp * 16 + gg;
    const int row1g = row0g + 8;

    for (int kt = 0; kt < ktiles; kt++) {
        const int kbase = kt * 32;
        const unsigned ksBase = (unsigned)__cvta_generic_to_shared(sm + ((kt & 1) ? BKS1 : BKS0));
        const unsigned vsBase = (unsigned)__cvta_generic_to_shared(sm + ((kt & 1) ? BVS1 : BVS0));

        if (kt + 1 < ktiles) {
            unsigned* kd = sm + (((kt + 1) & 1) ? BKS1 : BKS0);
            unsigned* vd = sm + (((kt + 1) & 1) ? BVS1 : BVS0);
            int r = tid >> 3, seg = tid & 7;
            cp_async16(kd + r * STKW + seg * 4,
                       k + base + (size_t)(kbase + 32 + r) * 64 + seg * 8);
            int rv = tid >> 2, sv = tid & 3;
            cp_async16(vd + rv * STVW + sv * 4,
                       v + base + (size_t)rv * Tn + kbase + 32 + sv * 8);
            CP_COMMIT();
        }

        float s[4][4];
#pragma unroll
        for (int nt = 0; nt < 4; nt++)
#pragma unroll
            for (int r = 0; r < 4; r++) s[nt][r] = 0.f;
#pragma unroll
        for (int ks = 0; ks < 4; ks++) {
            unsigned bf[4][2];
#pragma unroll
            for (int nt = 0; nt < 4; nt++)
                ldsm2(bf[nt], ksBase + (((nt * 8 + lrS) * STKW + ks * 8 + lcS) << 2));
#pragma unroll
            for (int nt = 0; nt < 4; nt++) mma16(s[nt], qf[ks], bf[nt]);
        }

        if (kt >= 4 * qt) {
#pragma unroll
            for (int nt = 0; nt < 4; nt++) {
                int c0 = kbase + nt * 8 + 2 * qq;
                if (c0 > row0g)     s[nt][0] = -1e30f;
                if (c0 + 1 > row0g) s[nt][1] = -1e30f;
                if (c0 > row1g)     s[nt][2] = -1e30f;
                if (c0 + 1 > row1g) s[nt][3] = -1e30f;
            }
        }

        float rm0 = -1e30f, rm1 = -1e30f;
#pragma unroll
        for (int nt = 0; nt < 4; nt++) {
            rm0 = fmaxf(rm0, fmaxf(s[nt][0], s[nt][1]));
            rm1 = fmaxf(rm1, fmaxf(s[nt][2], s[nt][3]));
        }
        rm0 = fmaxf(rm0, __shfl_xor_sync(0xffffffffu, rm0, 1));
        rm0 = fmaxf(rm0, __shfl_xor_sync(0xffffffffu, rm0, 2));
        rm1 = fmaxf(rm1, __shfl_xor_sync(0xffffffffu, rm1, 1));
        rm1 = fmaxf(rm1, __shfl_xor_sync(0xffffffffu, rm1, 2));
        float nm0 = fmaxf(m0, rm0), nm1 = fmaxf(m1, rm1);
        float corr0 = __expf(m0 - nm0), corr1 = __expf(m1 - nm1);
        float rs0 = 0.f, rs1 = 0.f;
#pragma unroll
        for (int nt = 0; nt < 4; nt++) {
            s[nt][0] = __expf(s[nt][0] - nm0);
            s[nt][1] = __expf(s[nt][1] - nm0);
            s[nt][2] = __expf(s[nt][2] - nm1);
            s[nt][3] = __expf(s[nt][3] - nm1);
            rs0 += s[nt][0] + s[nt][1];
            rs1 += s[nt][2] + s[nt][3];
        }
        rs0 += __shfl_xor_sync(0xffffffffu, rs0, 1);
        rs0 += __shfl_xor_sync(0xffffffffu, rs0, 2);
        rs1 += __shfl_xor_sync(0xffffffffu, rs1, 1);
        rs1 += __shfl_xor_sync(0xffffffffu, rs1, 2);
        l0 = l0 * corr0 + rs0;
        l1 = l1 * corr1 + rs1;
        m0 = nm0; m1 = nm1;
#pragma unroll
        for (int nt = 0; nt < 8; nt++) {
            oacc[nt][0] *= corr0; oacc[nt][1] *= corr0;
            oacc[nt][2] *= corr1; oacc[nt][3] *= corr1;
        }

        unsigned pa[2][4];
        pa[0][0] = h2u(s[0][0], s[0][1]);
        pa[0][1] = h2u(s[0][2], s[0][3]);
        pa[0][2] = h2u(s[1][0], s[1][1]);
        pa[0][3] = h2u(s[1][2], s[1][3]);
        pa[1][0] = h2u(s[2][0], s[2][1]);
        pa[1][1] = h2u(s[2][2], s[2][3]);
        pa[1][2] = h2u(s[3][0], s[3][1]);
        pa[1][3] = h2u(s[3][2], s[3][3]);

#pragma unroll
        for (int ks = 0; ks < 2; ks++) {
#pragma unroll
            for (int nt = 0; nt < 8; nt++) {
                unsigned bf2[2];
                ldsm2(bf2, vsBase + (((nt * 8 + lrS) * STVW + ks * 8 + lcS) << 2));
                mma16(oacc[nt], pa[ks], bf2);
            }
        }

        if (kt + 1 < ktiles) {
            CP_WAIT0();
            __syncthreads();
        }
    }

    const float inv0 = 1.f / l0, inv1 = 1.f / l1;
    const int b = bh / Hn, h = bh % Hn;
    __half* p0 = o + ((size_t)(b * Tn + row0g)) * Cn + h * 64;
    __half* p1 = o + ((size_t)(b * Tn + row1g)) * Cn + h * 64;
#pragma unroll
    for (int nt = 0; nt < 8; nt++) {
        *(__half2*)(p0 + nt * 8 + 2 * qq) = __floats2half2_rn(oacc[nt][0] * inv0, oacc[nt][1] * inv0);
        *(__half2*)(p1 + nt * 8 + 2 * qq) = __floats2half2_rn(oacc[nt][2] * inv1, oacc[nt][3] * inv1);
    }
}

// ---------------- fused residual + LayerNorm: 2 rows per 256-thread block ---------
__global__ __launch_bounds__(256) void ln_res_k(
    const float* __restrict__ x, const float* __restrict__ y,
    const float* __restrict__ g, const float* __restrict__ bb,
    float* __restrict__ out, __half* __restrict__ out16)
{
    __shared__ float red[8];
    const int half = threadIdx.x >> 7;
    const int tid = threadIdx.x & 127;
    const int row = blockIdx.x * 2 + half;
    const size_t base = (size_t)row * Cn;
    float v0 = x[base + tid]       + y[base + tid];
    float v1 = x[base + tid + 128] + y[base + tid + 128];
    float v2 = x[base + tid + 256] + y[base + tid + 256];

    float s = v0 + v1 + v2;
    for (int o = 16; o > 0; o >>= 1) s += __shfl_xor_sync(0xffffffffu, s, o);
    if ((tid & 31) == 0) red[half * 4 + (tid >> 5)] = s;
    __syncthreads();
    float mean = (red[half * 4] + red[half * 4 + 1] + red[half * 4 + 2] + red[half * 4 + 3]) * (1.f / Cn);
    __syncthreads();

    float d0 = v0 - mean, d1 = v1 - mean, d2 = v2 - mean;
    float sq = d0 * d0 + d1 * d1 + d2 * d2;
    for (int o = 16; o > 0; o >>= 1) sq += __shfl_xor_sync(0xffffffffu, sq, o);
    if ((tid & 31) == 0) red[half * 4 + (tid >> 5)] = sq;
    __syncthreads();
    float var = (red[half * 4] + red[half * 4 + 1] + red[half * 4 + 2] + red[half * 4 + 3]) * (1.f / Cn);
    float inv = rsqrtf(var + EPSn);

    float o0 = g[tid]       * d0 * inv + bb[tid];
    float o1 = g[tid + 128] * d1 * inv + bb[tid + 128];
    float o2 = g[tid + 256] * d2 * inv + bb[tid + 256];
    out[base + tid]       = o0;
    out[base + tid + 128] = o1;
    out[base + tid + 256] = o2;
    if (out16) {
        out16[base + tid]       = __float2half(o0);
        out16[base + tid + 128] = __float2half(o1);
        out16[base + tid + 256] = __float2half(o2);
    }
}

// ---------------- host orchestration ----------------
extern "C" void kernel_launch(void* const* d_in, const int* in_sizes, int n_in,
                              void* d_out, int out_size)
{
    (void)in_sizes; (void)n_in; (void)out_size;
    const float* x    = (const float*)d_in[0];
    const float* q1w  = (const float*)d_in[1];
    const float* q1b  = (const float*)d_in[2];
    const float* k1w  = (const float*)d_in[3];
    const float* k1b  = (const float*)d_in[4];
    const float* v1w  = (const float*)d_in[5];
    const float* v1b  = (const float*)d_in[6];
    const float* p1w  = (const float*)d_in[7];
    const float* p1b  = (const float*)d_in[8];
    const float* ln1g = (const float*)d_in[9];
    const float* ln1b = (const float*)d_in[10];
    const float* q2w  = (const float*)d_in[11];
    const float* q2b  = (const float*)d_in[12];
    const float* k2w  = (const float*)d_in[13];
    const float* k2b  = (const float*)d_in[14];
    const float* v2w  = (const float*)d_in[15];
    const float* v2b  = (const float*)d_in[16];
    const float* p2w  = (const float*)d_in[17];
    const float* p2b  = (const float*)d_in[18];
    const float* ln2g = (const float*)d_in[19];
    const float* ln2b = (const float*)d_in[20];
    const float* f1w  = (const float*)d_in[21];
    const float* f1b  = (const float*)d_in[22];
    const float* f2w  = (const float*)d_in[23];
    const float* f2b  = (const float*)d_in[24];
    const float* ln3g = (const float*)d_in[25];
    const float* ln3b = (const float*)d_in[26];
    float* out = (float*)d_out;

    __half *pwqkv1, *pwqkv2, *pwp1, *pwp2, *pwf1, *pwf2;
    __half *px16, *po16, *pr16, *ph16, *pq16, *pk16, *pv16t;
    float *pbqkv1, *pbqkv2, *pp, *pr1, *pr2;
    cudaGetSymbolAddress((void**)&pwqkv1, g_wqkv1);
    cudaGetSymbolAddress((void**)&pwqkv2, g_wqkv2);
    cudaGetSymbolAddress((void**)&pwp1, g_wp1);
    cudaGetSymbolAddress((void**)&pwp2, g_wp2);
    cudaGetSymbolAddress((void**)&pwf1, g_wf1t);
    cudaGetSymbolAddress((void**)&pwf2, g_wf2t);
    cudaGetSymbolAddress((void**)&px16, g_x16);
    cudaGetSymbolAddress((void**)&po16, g_o16);
    cudaGetSymbolAddress((void**)&pr16, g_r16);
    cudaGetSymbolAddress((void**)&ph16, g_h16);
    cudaGetSymbolAddress((void**)&pq16, g_q16);
    cudaGetSymbolAddress((void**)&pk16, g_k16);
    cudaGetSymbolAddress((void**)&pv16t, g_v16t);
    cudaGetSymbolAddress((void**)&pbqkv1, g_bqkv1);
    cudaGetSymbolAddress((void**)&pbqkv2, g_bqkv2);
    cudaGetSymbolAddress((void**)&pp,  g_p);
    cudaGetSymbolAddress((void**)&pr1, g_r1);
    cudaGetSymbolAddress((void**)&pr2, g_r2);

    prep_all<<<(PTOT + 255) / 256, 256>>>(
        x, px16,
        q1w, k1w, v1w, pwqkv1,
        q2w, k2w, v2w, pwqkv2,
        p1w, pwp1, p2w, pwp2,
        f1w, pwf1, f2w, pwf2,
        q1b, k1b, v1b, pbqkv1,
        q2b, k2b, v2b, pbqkv2);

    auto run_layer = [&](const float* xin_f32, const __half* xin_f16,
                         const __half* wqkv, const float* bqkv, const __half* wp,
                         const float* pb, const float* lng, const float* lnb,
                         float* rout, __half* rout16) {
        gemm_f16<<<dim3(3 * Cn / 128, BTn / 128), 256>>>(
            xin_f16, wqkv, bqkv, nullptr, nullptr, BTn, 3 * Cn, Cn, 2, pq16, pk16, pv16t);
        attn_mma<<<dim3(Tn / 128, Bn * Hn), 256>>>(pq16, pk16, pv16t, po16);
        gemm_f16<<<dim3(Cn / 128, BTn / 128), 256>>>(
            po16, wp, pb, pp, nullptr, BTn, Cn, Cn, 0, nullptr, nullptr, nullptr);
        ln_res_k<<<BTn / 2, 256>>>(xin_f32, pp, lng, lnb, rout, rout16);
    };

    run_layer(x,   px16, pwqkv1, pbqkv1, pwp1, p1b, ln1g, ln1b, pr1, pr16);
    run_layer(pr1, pr16, pwqkv2, pbqkv2, pwp2, p2b, ln2g, ln2b, pr2, pr16);

    gemm_f16<<<dim3(FFn / 128, BTn / 128), 256>>>(
        pr16, pwf1, f1b, nullptr, ph16, BTn, FFn, Cn, 1, nullptr, nullptr, nullptr);
    gemm_f16<<<dim3(Cn / 128, BTn / 128), 256>>>(
        ph16, pwf2, f2b, pp, nullptr, BTn, Cn, FFn, 0, nullptr, nullptr, nullptr);
    ln_res_k<<<BTn / 2, 256>>>(pr2, pp, ln3g, ln3b, out, nullptr);
}

// round 13
// speedup vs baseline: 1.5644x; 1.5644x over previous
#include <cuda_runtime.h>
#include <cuda_fp16.h>
#include <math.h>

#define Bn 64
#define Tn 512
#define Cn 384
#define Hn 6
#define HDn 64
#define FFn 1536
#define BTn (Bn*Tn)
#define EPSn 1e-5f

#define SWS 20    // gemm smem row stride (u32 words)

// fp16 attention smem (u32 word strides)
#define STKW 36
#define STVW 20
#define BKS0 0
#define BVS0 (32*STKW)
#define BKS1 (BVS0 + 64*STVW)
#define BVS1 (BKS1 + 32*STKW)
#define BTOT (BVS1 + 64*STVW)

// ---------------- scratch ----------------
__device__ __half g_wqkv1[3*Cn*Cn];
__device__ __half g_wqkv2[3*Cn*Cn];
__device__ __half g_wp1[Cn*Cn];
__device__ __half g_wp2[Cn*Cn];
__device__ __half g_wf1t[FFn*Cn];
__device__ __half g_wf2t[Cn*FFn];
__device__ float  g_bqkv1[3*Cn];
__device__ float  g_bqkv2[3*Cn];
__device__ __half g_x16[(size_t)BTn*Cn];
__device__ __half g_o16[(size_t)BTn*Cn];
__device__ __half g_r16[(size_t)BTn*Cn];
__device__ __half g_h16[(size_t)BTn*FFn];
__device__ __half g_y16[(size_t)BTn*Cn];         // fp16 residual delta (proj/ff2 out)
__device__ __half g_q16[(size_t)Bn*Hn*Tn*HDn];
__device__ __half g_k16[(size_t)Bn*Hn*Tn*HDn];
__device__ __half g_v16t[(size_t)Bn*Hn*HDn*Tn];
__device__ float g_r1[(size_t)BTn*Cn];
__device__ float g_r2[(size_t)BTn*Cn];

// ---------------- fused prep ----------------
#define SEG0 (BTn*Cn)
#define SEG1 (3*Cn*Cn)
#define SEG2 (3*Cn*Cn)
#define SEG3 (Cn*Cn)
#define SEG4 (Cn*Cn)
#define SEG5 (FFn*Cn)
#define SEG6 (Cn*FFn)
#define SEG7 (3*Cn)
#define SEG8 (3*Cn)
#define PTOT (SEG0+SEG1+SEG2+SEG3+SEG4+SEG5+SEG6+SEG7+SEG8)

__device__ __forceinline__ void pack_qkv_w(const float* qw, const float* kw,
                                           const float* vw, __half* o, int i) {
    int n = i / Cn, k = i % Cn;
    int mat = n / Cn, local = n % Cn;
    int h = local >> 6, d = local & 63;
    const float* w = (mat == 0) ? qw : (mat == 1) ? kw : vw;
    o[i] = __float2half(w[((size_t)h * Cn + k) * HDn + d]);
}
__device__ __forceinline__ void pack_wt(const float* w, __half* o, int N, int K, int i) {
    int n = i / K, k = i % K;
    o[i] = __float2half(w[(size_t)k * N + n]);
}

__global__ void prep_all(
    const float* __restrict__ x, __half* __restrict__ x16,
    const float* __restrict__ q1w, const float* __restrict__ k1w, const float* __restrict__ v1w,
    __half* __restrict__ wqkv1,
    const float* __restrict__ q2w, const float* __restrict__ k2w, const float* __restrict__ v2w,
    __half* __restrict__ wqkv2,
    const float* __restrict__ p1w, __half* __restrict__ wp1,
    const float* __restrict__ p2w, __half* __restrict__ wp2,
    const float* __restrict__ f1w, __half* __restrict__ wf1,
    const float* __restrict__ f2w, __half* __restrict__ wf2,
    const float* __restrict__ q1b, const float* __restrict__ k1b, const float* __restrict__ v1b,
    float* __restrict__ bqkv1,
    const float* __restrict__ q2b, const float* __restrict__ k2b, const float* __restrict__ v2b,
    float* __restrict__ bqkv2)
{
    int i = blockIdx.x * blockDim.x + threadIdx.x;
    if (i >= PTOT) return;
    if (i < SEG0) { x16[i] = __float2half(x[i]); return; }
    i -= SEG0;
    if (i < SEG1) { pack_qkv_w(q1w, k1w, v1w, wqkv1, i); return; }
    i -= SEG1;
    if (i < SEG2) { pack_qkv_w(q2w, k2w, v2w, wqkv2, i); return; }
    i -= SEG2;
    if (i < SEG3) { pack_wt(p1w, wp1, Cn, Cn, i); return; }
    i -= SEG3;
    if (i < SEG4) { pack_wt(p2w, wp2, Cn, Cn, i); return; }
    i -= SEG4;
    if (i < SEG5) { pack_wt(f1w, wf1, FFn, Cn, i); return; }
    i -= SEG5;
    if (i < SEG6) { pack_wt(f2w, wf2, Cn, FFn, i); return; }
    i -= SEG6;
    if (i < SEG7) {
        const float* b = (i < Cn) ? q1b : (i < 2 * Cn) ? k1b : v1b;
        bqkv1[i] = b[i % Cn]; return;
    }
    i -= SEG7;
    {
        const float* b = (i < Cn) ? q2b : (i < 2 * Cn) ? k2b : v2b;
        bqkv2[i] = b[i % Cn];
    }
}

// ---------------- mma / ldmatrix / async helpers ----------------
__device__ __forceinline__ void mma16(float* d, const unsigned* a, const unsigned* b) {
    asm("mma.sync.aligned.m16n8k16.row.col.f32.f16.f16.f32 "
        "{%0,%1,%2,%3},{%4,%5,%6,%7},{%8,%9},{%0,%1,%2,%3};"
        : "+f"(d[0]), "+f"(d[1]), "+f"(d[2]), "+f"(d[3])
        : "r"(a[0]), "r"(a[1]), "r"(a[2]), "r"(a[3]), "r"(b[0]), "r"(b[1]));
}
__device__ __forceinline__ void ldsm4(unsigned* r, unsigned addr) {
    asm volatile("ldmatrix.sync.aligned.m8n8.x4.shared.b16 {%0,%1,%2,%3}, [%4];"
        : "=r"(r[0]), "=r"(r[1]), "=r"(r[2]), "=r"(r[3]) : "r"(addr));
}
__device__ __forceinline__ void ldsm2(unsigned* r, unsigned addr) {
    asm volatile("ldmatrix.sync.aligned.m8n8.x2.shared.b16 {%0,%1}, [%2];"
        : "=r"(r[0]), "=r"(r[1]) : "r"(addr));
}
__device__ __forceinline__ unsigned h2u(float a, float b) {
    __half2 h = __floats2half2_rn(a, b);
    return *(unsigned*)&h;
}
__device__ __forceinline__ void cp_async16(void* smem_dst, const void* gsrc) {
    unsigned saddr = (unsigned)__cvta_generic_to_shared(smem_dst);
    asm volatile("cp.async.ca.shared.global [%0], [%1], 16;\n" :: "r"(saddr), "l"(gsrc));
}
#define CP_COMMIT() asm volatile("cp.async.commit_group;\n" ::: "memory")
#define CP_WAIT0()  asm volatile("cp.async.wait_group 0;\n" ::: "memory")

// ---------------- fp16 GEMM: R10-exact core (4-stage, pair-iterated) --------------
// flags: 0 = fp16 out (no relu); 1 = relu + fp16 out; 2 = qkv scatter fp16 (+rope)
__global__ __launch_bounds__(256) void gemm_f16(
    const __half* __restrict__ A, const __half* __restrict__ Bm,
    const float* __restrict__ bias,
    __half* __restrict__ Cout16,
    int M, int N, int K, int flags,
    __half* __restrict__ oq, __half* __restrict__ ok, __half* __restrict__ ov)
{
    __shared__ __align__(16) unsigned As[4][128 * SWS];
    __shared__ __align__(16) unsigned Bs[4][128 * SWS];

    const int tid = threadIdx.x;
    const int lane = tid & 31, warp = tid >> 5;
    const int warpM = warp >> 2, warpN = warp & 3;
    const int bm = blockIdx.y * 128, bn = blockIdx.x * 128;
    const int qq = lane & 3, gg = lane >> 2;

    const int sRow = tid >> 1;
    const int sOff = (tid & 1) * 8;
    const __half* Ap = A + (size_t)(bm + sRow) * K + (tid & 1) * 16;
    const __half* Bp = Bm + (size_t)(bn + sRow) * K + (tid & 1) * 16;

    const int arS = warpM * 64 + (lane & 7) + ((lane >> 3) & 1) * 8;
    const int acS = (lane >> 4) * 4;
    const int brS = warpN * 32 + (lane & 7);
    const int bcS = ((lane >> 3) & 1) * 4;

    unsigned aBase[4], bBase[4];
#pragma unroll
    for (int s = 0; s < 4; s++) {
        aBase[s] = (unsigned)__cvta_generic_to_shared(As[s]);
        bBase[s] = (unsigned)__cvta_generic_to_shared(Bs[s]);
    }

    float acc[4][4][4];
#pragma unroll
    for (int i = 0; i < 4; i++)
#pragma unroll
        for (int j = 0; j < 4; j++)
#pragma unroll
            for (int r = 0; r < 4; r++) acc[i][j][r] = 0.f;

    const int KT = K >> 5;   // even (12 or 48)

    {
        unsigned* as0 = As[0]; unsigned* bs0 = Bs[0];
        cp_async16(as0 + sRow * SWS + sOff,     Ap);
        cp_async16(as0 + sRow * SWS + sOff + 4, Ap + 8);
        cp_async16(bs0 + sRow * SWS + sOff,     Bp);
        cp_async16(bs0 + sRow * SWS + sOff + 4, Bp + 8);
        unsigned* as1 = As[1]; unsigned* bs1 = Bs[1];
        cp_async16(as1 + sRow * SWS + sOff,     Ap + 32);
        cp_async16(as1 + sRow * SWS + sOff + 4, Ap + 40);
        cp_async16(bs1 + sRow * SWS + sOff,     Bp + 32);
        cp_async16(bs1 + sRow * SWS + sOff + 4, Bp + 40);
    }
    CP_COMMIT();

    for (int kt2 = 0; kt2 < KT; kt2 += 2) {
        CP_WAIT0();
        __syncthreads();

        if (kt2 + 2 < KT) {
            int stA = (kt2 + 2) & 3, stB = (kt2 + 3) & 3;
            const __half* apA = Ap + (size_t)(kt2 + 2) * 32;
            const __half* bpA = Bp + (size_t)(kt2 + 2) * 32;
            unsigned* as = As[stA]; unsigned* bs = Bs[stA];
            cp_async16(as + sRow * SWS + sOff,     apA);
            cp_async16(as + sRow * SWS + sOff + 4, apA + 8);
            cp_async16(bs + sRow * SWS + sOff,     bpA);
            cp_async16(bs + sRow * SWS + sOff + 4, bpA + 8);
            unsigned* as2 = As[stB]; unsigned* bs2 = Bs[stB];
            cp_async16(as2 + sRow * SWS + sOff,     apA + 32);
            cp_async16(as2 + sRow * SWS + sOff + 4, apA + 40);
            cp_async16(bs2 + sRow * SWS + sOff,     bpA + 32);
            cp_async16(bs2 + sRow * SWS + sOff + 4, bpA + 40);
            CP_COMMIT();
        }

#pragma unroll
        for (int sub = 0; sub < 2; sub++) {
            const unsigned ab = aBase[(kt2 + sub) & 3];
            const unsigned bb = bBase[(kt2 + sub) & 3];
#pragma unroll
            for (int ko = 0; ko < 16; ko += 8) {
                unsigned af[4][4], bf[4][2];
#pragma unroll
                for (int mi = 0; mi < 4; mi++)
                    ldsm4(af[mi], ab + (((mi * 16 + arS) * SWS + ko + acS) << 2));
#pragma unroll
                for (int ni = 0; ni < 4; ni++)
                    ldsm2(bf[ni], bb + (((ni * 8 + brS) * SWS + ko + bcS) << 2));
#pragma unroll
                for (int mi = 0; mi < 4; mi++)
#pragma unroll
                    for (int ni = 0; ni < 4; ni++)
                        mma16(acc[mi][ni], af[mi], bf[ni]);
            }
        }
    }

    const float scale = 0.051031036307982884f;   // 1/sqrt(384)
#pragma unroll
    for (int mi = 0; mi < 4; mi++) {
        int row0 = bm + warpM * 64 + mi * 16 + gg;
        float sn[2], cs[2];
        if (flags == 2) {
            sincosf((float)(row0 & 511), &sn[0], &cs[0]);
            sincosf((float)((row0 + 8) & 511), &sn[1], &cs[1]);
        }
#pragma unroll
        for (int ni = 0; ni < 4; ni++) {
            int col = bn + warpN * 32 + ni * 8 + qq * 2;
            float b0 = bias[col], b1 = bias[col + 1];
#pragma unroll
            for (int half = 0; half < 2; half++) {
                int row = row0 + half * 8;
                float xr = acc[mi][ni][half * 2 + 0] + b0;
                float xi = acc[mi][ni][half * 2 + 1] + b1;
                if (flags == 2) {
                    int mat = col / Cn;
                    if (mat < 2) {
                        float nr = cs[half] * xr - sn[half] * xi;
                        float ni2 = sn[half] * xr + cs[half] * xi;
                        xr = nr; xi = ni2;
                    }
                    int local = col - mat * Cn;
                    int h = local >> 6, d = local & 63;
                    int bbv = row >> 9, t = row & 511;
                    if (mat == 0) {
                        __half2 hv = __floats2half2_rn(xr * scale, xi * scale);
                        *(__half2*)(oq + ((size_t)(bbv * Hn + h) * Tn + t) * HDn + d) = hv;
                    } else if (mat == 1) {
                        __half2 hv = __floats2half2_rn(xr, xi);
                        *(__half2*)(ok + ((size_t)(bbv * Hn + h) * Tn + t) * HDn + d) = hv;
                    } else {
                        size_t vb = ((size_t)(bbv * Hn + h) * HDn + d) * Tn + t;
                        ov[vb]      = __float2half(xr);
                        ov[vb + Tn] = __float2half(xi);
                    }
                } else {
                    if (flags == 1) { xr = fmaxf(xr, 0.f); xi = fmaxf(xi, 0.f); }
                    __half2* p = (__half2*)(Cout16 + (size_t)row * N + col);
                    *p = __floats2half2_rn(xr, xi);
                }
            }
        }
    }
}

// ---------------- fp16 causal flash attention: 128-query tile (R10-exact) ---------
__global__ __launch_bounds__(256) void attn_mma(
    const __half* __restrict__ q, const __half* __restrict__ k,
    const __half* __restrict__ v, __half* __restrict__ o)
{
    __shared__ __align__(16) unsigned sm[BTOT];

    const int bh = blockIdx.y;
    const int qt = gridDim.x - 1 - blockIdx.x;
    const int tid = threadIdx.x;
    const int warp = tid >> 5, lane = tid & 31;
    const int gg = lane >> 2, qq = lane & 3;
    const size_t base = (size_t)bh * Tn * HDn;
    const int q0 = qt * 128;
    const int ktiles = 4 * qt + 4;

    const int lrS = lane & 7;
    const int lcS = ((lane >> 3) & 1) * 4;

    {
        unsigned* kd = sm + BKS0;
        unsigned* vd = sm + BVS0;
        int r = tid >> 3, seg = tid & 7;
        cp_async16(kd + r * STKW + seg * 4, k + base + (size_t)r * 64 + seg * 8);
        int rv = tid >> 2, sv = tid & 3;
        cp_async16(vd + rv * STVW + sv * 4, v + base + (size_t)rv * Tn + sv * 8);
        CP_COMMIT();
    }

    unsigned qf[4][4];
    {
        const __half* q0p = q + base + (size_t)(q0 + warp * 16 + gg) * 64;
        const __half* q1p = q0p + 8 * 64;
#pragma unroll
        for (int ks = 0; ks < 4; ks++) {
            qf[ks][0] = *(const unsigned*)(q0p + ks * 16 + 2 * qq);
            qf[ks][1] = *(const unsigned*)(q1p + ks * 16 + 2 * qq);
            qf[ks][2] = *(const unsigned*)(q0p + ks * 16 + 2 * qq + 8);
            qf[ks][3] = *(const unsigned*)(q1p + ks * 16 + 2 * qq + 8);
        }
    }
    CP_WAIT0();
    __syncthreads();

    float oacc[8][4];
#pragma unroll
    for (int i = 0; i < 8; i++)
#pragma unroll
        for (int r = 0; r < 4; r++) oacc[i][r] = 0.f;
    float m0 = -INFINITY, m1 = -INFINITY, l0 = 0.f, l1 = 0.f;

    const int row0g = q0 + warp * 16 + gg;
    const int row1g = row0g + 8;

    for (int kt = 0; kt < ktiles; kt++) {
        const int kbase = kt * 32;
        const unsigned ksBase = (unsigned)__cvta_generic_to_shared(sm + ((kt & 1) ? BKS1 : BKS0));
        const unsigned vsBase = (unsigned)__cvta_generic_to_shared(sm + ((kt & 1) ? BVS1 : BVS0));

        if (kt + 1 < ktiles) {
            unsigned* kd = sm + (((kt + 1) & 1) ? BKS1 : BKS0);
            unsigned* vd = sm + (((kt + 1) & 1) ? BVS1 : BVS0);
            int r = tid >> 3, seg = tid & 7;
            cp_async16(kd + r * STKW + seg * 4,
                       k + base + (size_t)(kbase + 32 + r) * 64 + seg * 8);
            int rv = tid >> 2, sv = tid & 3;
            cp_async16(vd + rv * STVW + sv * 4,
                       v + base + (size_t)rv * Tn + kbase + 32 + sv * 8);
            CP_COMMIT();
        }

        float s[4][4];
#pragma unroll
        for (int nt = 0; nt < 4; nt++)
#pragma unroll
            for (int r = 0; r < 4; r++) s[nt][r] = 0.f;
#pragma unroll
        for (int ks = 0; ks < 4; ks++) {
            unsigned bf[4][2];
#pragma unroll
            for (int nt = 0; nt < 4; nt++)
                ldsm2(bf[nt], ksBase + (((nt * 8 + lrS) * STKW + ks * 8 + lcS) << 2));
#pragma unroll
            for (int nt = 0; nt < 4; nt++) mma16(s[nt], qf[ks], bf[nt]);
        }

        if (kt >= 4 * qt) {
#pragma unroll
            for (int nt = 0; nt < 4; nt++) {
                int c0 = kbase + nt * 8 + 2 * qq;
                if (c0 > row0g)     s[nt][0] = -1e30f;
                if (c0 + 1 > row0g) s[nt][1] = -1e30f;
                if (c0 > row1g)     s[nt][2] = -1e30f;
                if (c0 + 1 > row1g) s[nt][3] = -1e30f;
            }
        }

        float rm0 = -1e30f, rm1 = -1e30f;
#pragma unroll
        for (int nt = 0; nt < 4; nt++) {
            rm0 = fmaxf(rm0, fmaxf(s[nt][0], s[nt][1]));
            rm1 = fmaxf(rm1, fmaxf(s[nt][2], s[nt][3]));
        }
        rm0 = fmaxf(rm0, __shfl_xor_sync(0xffffffffu, rm0, 1));
        rm0 = fmaxf(rm0, __shfl_xor_sync(0xffffffffu, rm0, 2));
        rm1 = fmaxf(rm1, __shfl_xor_sync(0xffffffffu, rm1, 1));
        rm1 = fmaxf(rm1, __shfl_xor_sync(0xffffffffu, rm1, 2));
        float nm0 = fmaxf(m0, rm0), nm1 = fmaxf(m1, rm1);
        float corr0 = __expf(m0 - nm0), corr1 = __expf(m1 - nm1);
        float rs0 = 0.f, rs1 = 0.f;
#pragma unroll
        for (int nt = 0; nt < 4; nt++) {
            s[nt][0] = __expf(s[nt][0] - nm0);
            s[nt][1] = __expf(s[nt][1] - nm0);
            s[nt][2] = __expf(s[nt][2] - nm1);
            s[nt][3] = __expf(s[nt][3] - nm1);
            rs0 += s[nt][0] + s[nt][1];
            rs1 += s[nt][2] + s[nt][3];
        }
        rs0 += __shfl_xor_sync(0xffffffffu, rs0, 1);
        rs0 += __shfl_xor_sync(0xffffffffu, rs0, 2);
        rs1 += __shfl_xor_sync(0xffffffffu, rs1, 1);
        rs1 += __shfl_xor_sync(0xffffffffu, rs1, 2);
        l0 = l0 * corr0 + rs0;
        l1 = l1 * corr1 + rs1;
        m0 = nm0; m1 = nm1;
#pragma unroll
        for (int nt = 0; nt < 8; nt++) {
            oacc[nt][0] *= corr0; oacc[nt][1] *= corr0;
            oacc[nt][2] *= corr1; oacc[nt][3] *= corr1;
        }

        unsigned pa[2][4];
        pa[0][0] = h2u(s[0][0], s[0][1]);
        pa[0][1] = h2u(s[0][2], s[0][3]);
        pa[0][2] = h2u(s[1][0], s[1][1]);
        pa[0][3] = h2u(s[1][2], s[1][3]);
        pa[1][0] = h2u(s[2][0], s[2][1]);
        pa[1][1] = h2u(s[2][2], s[2][3]);
        pa[1][2] = h2u(s[3][0], s[3][1]);
        pa[1][3] = h2u(s[3][2], s[3][3]);

#pragma unroll
        for (int ks = 0; ks < 2; ks++) {
#pragma unroll
            for (int nt = 0; nt < 8; nt++) {
                unsigned bf2[2];
                ldsm2(bf2, vsBase + (((nt * 8 + lrS) * STVW + ks * 8 + lcS) << 2));
                mma16(oacc[nt], pa[ks], bf2);
            }
        }

        if (kt + 1 < ktiles) {
            CP_WAIT0();
            __syncthreads();
        }
    }

    const float inv0 = 1.f / l0, inv1 = 1.f / l1;
    const int b = bh / Hn, h = bh % Hn;
    __half* p0 = o + ((size_t)(b * Tn + row0g)) * Cn + h * 64;
    __half* p1 = o + ((size_t)(b * Tn + row1g)) * Cn + h * 64;
#pragma unroll
    for (int nt = 0; nt < 8; nt++) {
        *(__half2*)(p0 + nt * 8 + 2 * qq) = __floats2half2_rn(oacc[nt][0] * inv0, oacc[nt][1] * inv0);
        *(__half2*)(p1 + nt * 8 + 2 * qq) = __floats2half2_rn(oacc[nt][2] * inv1, oacc[nt][3] * inv1);
    }
}

// ---------------- fused residual + LayerNorm: y is fp16, 2 rows/block -------------
__global__ __launch_bounds__(256) void ln_res_k(
    const float* __restrict__ x, const __half* __restrict__ y,
    const float* __restrict__ g, const float* __restrict__ bb,
    float* __restrict__ out, __half* __restrict__ out16)
{
    __shared__ float red[8];
    const int half = threadIdx.x >> 7;
    const int tid = threadIdx.x & 127;
    const int row = blockIdx.x * 2 + half;
    const size_t base = (size_t)row * Cn;
    float v0 = x[base + tid]       + __half2float(y[base + tid]);
    float v1 = x[base + tid + 128] + __half2float(y[base + tid + 128]);
    float v2 = x[base + tid + 256] + __half2float(y[base + tid + 256]);

    float s = v0 + v1 + v2;
    for (int o = 16; o > 0; o >>= 1) s += __shfl_xor_sync(0xffffffffu, s, o);
    if ((tid & 31) == 0) red[half * 4 + (tid >> 5)] = s;
    __syncthreads();
    float mean = (red[half * 4] + red[half * 4 + 1] + red[half * 4 + 2] + red[half * 4 + 3]) * (1.f / Cn);
    __syncthreads();

    float d0 = v0 - mean, d1 = v1 - mean, d2 = v2 - mean;
    float sq = d0 * d0 + d1 * d1 + d2 * d2;
    for (int o = 16; o > 0; o >>= 1) sq += __shfl_xor_sync(0xffffffffu, sq, o);
    if ((tid & 31) == 0) red[half * 4 + (tid >> 5)] = sq;
    __syncthreads();
    float var = (red[half * 4] + red[half * 4 + 1] + red[half * 4 + 2] + red[half * 4 + 3]) * (1.f / Cn);
    float inv = rsqrtf(var + EPSn);

    float o0 = g[tid]       * d0 * inv + bb[tid];
    float o1 = g[tid + 128] * d1 * inv + bb[tid + 128];
    float o2 = g[tid + 256] * d2 * inv + bb[tid + 256];
    out[base + tid]       = o0;
    out[base + tid + 128] = o1;
    out[base + tid + 256] = o2;
    if (out16) {
        out16[base + tid]       = __float2half(o0);
        out16[base + tid + 128] = __float2half(o1);
        out16[base + tid + 256] = __float2half(o2);
    }
}

// ---------------- host orchestration ----------------
extern "C" void kernel_launch(void* const* d_in, const int* in_sizes, int n_in,
                              void* d_out, int out_size)
{
    (void)in_sizes; (void)n_in; (void)out_size;
    const float* x    = (const float*)d_in[0];
    const float* q1w  = (const float*)d_in[1];
    const float* q1b  = (const float*)d_in[2];
    const float* k1w  = (const float*)d_in[3];
    const float* k1b  = (const float*)d_in[4];
    const float* v1w  = (const float*)d_in[5];
    const float* v1b  = (const float*)d_in[6];
    const float* p1w  = (const float*)d_in[7];
    const float* p1b  = (const float*)d_in[8];
    const float* ln1g = (const float*)d_in[9];
    const float* ln1b = (const float*)d_in[10];
    const float* q2w  = (const float*)d_in[11];
    const float* q2b  = (const float*)d_in[12];
    const float* k2w  = (const float*)d_in[13];
    const float* k2b  = (const float*)d_in[14];
    const float* v2w  = (const float*)d_in[15];
    const float* v2b  = (const float*)d_in[16];
    const float* p2w  = (const float*)d_in[17];
    const float* p2b  = (const float*)d_in[18];
    const float* ln2g = (const float*)d_in[19];
    const float* ln2b = (const float*)d_in[20];
    const float* f1w  = (const float*)d_in[21];
    const float* f1b  = (const float*)d_in[22];
    const float* f2w  = (const float*)d_in[23];
    const float* f2b  = (const float*)d_in[24];
    const float* ln3g = (const float*)d_in[25];
    const float* ln3b = (const float*)d_in[26];
    float* out = (float*)d_out;

    __half *pwqkv1, *pwqkv2, *pwp1, *pwp2, *pwf1, *pwf2;
    __half *px16, *po16, *pr16, *ph16, *py16, *pq16, *pk16, *pv16t;
    float *pbqkv1, *pbqkv2, *pr1, *pr2;
    cudaGetSymbolAddress((void**)&pwqkv1, g_wqkv1);
    cudaGetSymbolAddress((void**)&pwqkv2, g_wqkv2);
    cudaGetSymbolAddress((void**)&pwp1, g_wp1);
    cudaGetSymbolAddress((void**)&pwp2, g_wp2);
    cudaGetSymbolAddress((void**)&pwf1, g_wf1t);
    cudaGetSymbolAddress((void**)&pwf2, g_wf2t);
    cudaGetSymbolAddress((void**)&px16, g_x16);
    cudaGetSymbolAddress((void**)&po16, g_o16);
    cudaGetSymbolAddress((void**)&pr16, g_r16);
    cudaGetSymbolAddress((void**)&ph16, g_h16);
    cudaGetSymbolAddress((void**)&py16, g_y16);
    cudaGetSymbolAddress((void**)&pq16, g_q16);
    cudaGetSymbolAddress((void**)&pk16, g_k16);
    cudaGetSymbolAddress((void**)&pv16t, g_v16t);
    cudaGetSymbolAddress((void**)&pbqkv1, g_bqkv1);
    cudaGetSymbolAddress((void**)&pbqkv2, g_bqkv2);
    cudaGetSymbolAddress((void**)&pr1, g_r1);
    cudaGetSymbolAddress((void**)&pr2, g_r2);

    prep_all<<<(PTOT + 255) / 256, 256>>>(
        x, px16,
        q1w, k1w, v1w, pwqkv1,
        q2w, k2w, v2w, pwqkv2,
        p1w, pwp1, p2w, pwp2,
        f1w, pwf1, f2w, pwf2,
        q1b, k1b, v1b, pbqkv1,
        q2b, k2b, v2b, pbqkv2);

    auto run_layer = [&](const float* xin_f32, const __half* xin_f16,
                         const __half* wqkv, const float* bqkv, const __half* wp,
                         const float* pb, const float* lng, const float* lnb,
                         float* rout, __half* rout16) {
        gemm_f16<<<dim3(3 * Cn / 128, BTn / 128), 256>>>(
            xin_f16, wqkv, bqkv, nullptr, BTn, 3 * Cn, Cn, 2, pq16, pk16, pv16t);
        attn_mma<<<dim3(Tn / 128, Bn * Hn), 256>>>(pq16, pk16, pv16t, po16);
        gemm_f16<<<dim3(Cn / 128, BTn / 128), 256>>>(
            po16, wp, pb, py16, BTn, Cn, Cn, 0, nullptr, nullptr, nullptr);
        ln_res_k<<<BTn / 2, 256>>>(xin_f32, py16, lng, lnb, rout, rout16);
    };

    run_layer(x,   px16, pwqkv1, pbqkv1, pwp1, p1b, ln1g, ln1b, pr1, pr16);
    run_layer(pr1, pr16, pwqkv2, pbqkv2, pwp2, p2b, ln2g, ln2b, pr2, pr16);

    gemm_f16<<<dim3(FFn / 128, BTn / 128), 256>>>(
        pr16, pwf1, f1b, ph16, BTn, FFn, Cn, 1, nullptr, nullptr, nullptr);
    gemm_f16<<<dim3(Cn / 128, BTn / 128), 256>>>(
        ph16, pwf2, f2b, py16, BTn, Cn, FFn, 0, nullptr, nullptr, nullptr);
    ln_res_k<<<BTn / 2, 256>>>(pr2, py16, ln3g, ln3b, out, nullptr);
}

// round 14
// speedup vs baseline: 1.5807x; 1.0105x over previous
#include <cuda_runtime.h>
#include <cuda_fp16.h>
#include <math.h>

#define Bn 64
#define Tn 512
#define Cn 384
#define Hn 6
#define HDn 64
#define FFn 1536
#define BTn (Bn*Tn)
#define EPSn 1e-5f

#define SWS 20    // gemm smem row stride (u32 words)

// fp16 attention smem (u32 word strides), 64-key stages
#define ASTK 36
#define ASTV 36
#define AK0 0
#define AV0 (64*ASTK)
#define AK1 (2*64*ASTK)
#define AV1 (3*64*ASTK)
#define ATOT (4*64*ASTK)

// ---------------- scratch ----------------
__device__ __half g_wqkv1[3*Cn*Cn];
__device__ __half g_wqkv2[3*Cn*Cn];
__device__ __half g_wp1[Cn*Cn];
__device__ __half g_wp2[Cn*Cn];
__device__ __half g_wf1t[FFn*Cn];
__device__ __half g_wf2t[Cn*FFn];
__device__ float  g_bqkv1[3*Cn];
__device__ float  g_bqkv2[3*Cn];
__device__ float2 g_rope[Tn];
__device__ __half g_x16[(size_t)BTn*Cn];
__device__ __half g_o16[(size_t)BTn*Cn];
__device__ __half g_r16[(size_t)BTn*Cn];
__device__ __half g_h16[(size_t)BTn*FFn];
__device__ __half g_y16[(size_t)BTn*Cn];
__device__ __half g_q16[(size_t)Bn*Hn*Tn*HDn];
__device__ __half g_k16[(size_t)Bn*Hn*Tn*HDn];
__device__ __half g_v16t[(size_t)Bn*Hn*HDn*Tn];
__device__ float g_r1[(size_t)BTn*Cn];
__device__ float g_r2[(size_t)BTn*Cn];

// ---------------- fused prep ----------------
#define SEG0 (BTn*Cn)
#define SEG1 (3*Cn*Cn)
#define SEG2 (3*Cn*Cn)
#define SEG3 (Cn*Cn)
#define SEG4 (Cn*Cn)
#define SEG5 (FFn*Cn)
#define SEG6 (Cn*FFn)
#define SEG7 (3*Cn)
#define SEG8 (3*Cn)
#define SEG9 (Tn)
#define PTOT (SEG0+SEG1+SEG2+SEG3+SEG4+SEG5+SEG6+SEG7+SEG8+SEG9)

__device__ __forceinline__ void pack_qkv_w(const float* qw, const float* kw,
                                           const float* vw, __half* o, int i) {
    int n = i / Cn, k = i % Cn;
    int mat = n / Cn, local = n % Cn;
    int h = local >> 6, d = local & 63;
    const float* w = (mat == 0) ? qw : (mat == 1) ? kw : vw;
    o[i] = __float2half(w[((size_t)h * Cn + k) * HDn + d]);
}
__device__ __forceinline__ void pack_wt(const float* w, __half* o, int N, int K, int i) {
    int n = i / K, k = i % K;
    o[i] = __float2half(w[(size_t)k * N + n]);
}

__global__ void prep_all(
    const float* __restrict__ x, __half* __restrict__ x16,
    const float* __restrict__ q1w, const float* __restrict__ k1w, const float* __restrict__ v1w,
    __half* __restrict__ wqkv1,
    const float* __restrict__ q2w, const float* __restrict__ k2w, const float* __restrict__ v2w,
    __half* __restrict__ wqkv2,
    const float* __restrict__ p1w, __half* __restrict__ wp1,
    const float* __restrict__ p2w, __half* __restrict__ wp2,
    const float* __restrict__ f1w, __half* __restrict__ wf1,
    const float* __restrict__ f2w, __half* __restrict__ wf2,
    const float* __restrict__ q1b, const float* __restrict__ k1b, const float* __restrict__ v1b,
    float* __restrict__ bqkv1,
    const float* __restrict__ q2b, const float* __restrict__ k2b, const float* __restrict__ v2b,
    float* __restrict__ bqkv2,
    float2* __restrict__ rope)
{
    int i = blockIdx.x * blockDim.x + threadIdx.x;
    if (i >= PTOT) return;
    if (i < SEG0) { x16[i] = __float2half(x[i]); return; }
    i -= SEG0;
    if (i < SEG1) { pack_qkv_w(q1w, k1w, v1w, wqkv1, i); return; }
    i -= SEG1;
    if (i < SEG2) { pack_qkv_w(q2w, k2w, v2w, wqkv2, i); return; }
    i -= SEG2;
    if (i < SEG3) { pack_wt(p1w, wp1, Cn, Cn, i); return; }
    i -= SEG3;
    if (i < SEG4) { pack_wt(p2w, wp2, Cn, Cn, i); return; }
    i -= SEG4;
    if (i < SEG5) { pack_wt(f1w, wf1, FFn, Cn, i); return; }
    i -= SEG5;
    if (i < SEG6) { pack_wt(f2w, wf2, Cn, FFn, i); return; }
    i -= SEG6;
    if (i < SEG7) {
        const float* b = (i < Cn) ? q1b : (i < 2 * Cn) ? k1b : v1b;
        bqkv1[i] = b[i % Cn]; return;
    }
    i -= SEG7;
    if (i < SEG8) {
        const float* b = (i < Cn) ? q2b : (i < 2 * Cn) ? k2b : v2b;
        bqkv2[i] = b[i % Cn]; return;
    }
    i -= SEG8;
    {
        float s, c;
        sincosf((float)i, &s, &c);
        rope[i] = make_float2(c, s);
    }
}

// ---------------- mma / ldmatrix / async helpers ----------------
__device__ __forceinline__ void mma16(float* d, const unsigned* a, const unsigned* b) {
    asm("mma.sync.aligned.m16n8k16.row.col.f32.f16.f16.f32 "
        "{%0,%1,%2,%3},{%4,%5,%6,%7},{%8,%9},{%0,%1,%2,%3};"
        : "+f"(d[0]), "+f"(d[1]), "+f"(d[2]), "+f"(d[3])
        : "r"(a[0]), "r"(a[1]), "r"(a[2]), "r"(a[3]), "r"(b[0]), "r"(b[1]));
}
__device__ __forceinline__ void ldsm4(unsigned* r, unsigned addr) {
    asm volatile("ldmatrix.sync.aligned.m8n8.x4.shared.b16 {%0,%1,%2,%3}, [%4];"
        : "=r"(r[0]), "=r"(r[1]), "=r"(r[2]), "=r"(r[3]) : "r"(addr));
}
__device__ __forceinline__ void ldsm2(unsigned* r, unsigned addr) {
    asm volatile("ldmatrix.sync.aligned.m8n8.x2.shared.b16 {%0,%1}, [%2];"
        : "=r"(r[0]), "=r"(r[1]) : "r"(addr));
}
__device__ __forceinline__ unsigned h2u(float a, float b) {
    __half2 h = __floats2half2_rn(a, b);
    return *(unsigned*)&h;
}
__device__ __forceinline__ void cp_async16(void* smem_dst, const void* gsrc) {
    unsigned saddr = (unsigned)__cvta_generic_to_shared(smem_dst);
    asm volatile("cp.async.ca.shared.global [%0], [%1], 16;\n" :: "r"(saddr), "l"(gsrc));
}
#define CP_COMMIT() asm volatile("cp.async.commit_group;\n" ::: "memory")
#define CP_WAIT0()  asm volatile("cp.async.wait_group 0;\n" ::: "memory")

// ---------------- fp16 GEMM: R10-exact core (4-stage, pair-iterated) --------------
// flags: 0 = fp16 out (no relu); 1 = relu + fp16 out; 2 = qkv scatter fp16 (+rope)
__global__ __launch_bounds__(256) void gemm_f16(
    const __half* __restrict__ A, const __half* __restrict__ Bm,
    const float* __restrict__ bias,
    __half* __restrict__ Cout16,
    int M, int N, int K, int flags,
    __half* __restrict__ oq, __half* __restrict__ ok, __half* __restrict__ ov,
    const float2* __restrict__ rope)
{
    __shared__ __align__(16) unsigned As[4][128 * SWS];
    __shared__ __align__(16) unsigned Bs[4][128 * SWS];

    const int tid = threadIdx.x;
    const int lane = tid & 31, warp = tid >> 5;
    const int warpM = warp >> 2, warpN = warp & 3;
    const int bm = blockIdx.y * 128, bn = blockIdx.x * 128;
    const int qq = lane & 3, gg = lane >> 2;

    const int sRow = tid >> 1;
    const int sOff = (tid & 1) * 8;
    const __half* Ap = A + (size_t)(bm + sRow) * K + (tid & 1) * 16;
    const __half* Bp = Bm + (size_t)(bn + sRow) * K + (tid & 1) * 16;

    const int arS = warpM * 64 + (lane & 7) + ((lane >> 3) & 1) * 8;
    const int acS = (lane >> 4) * 4;
    const int brS = warpN * 32 + (lane & 7);
    const int bcS = ((lane >> 3) & 1) * 4;

    unsigned aBase[4], bBase[4];
#pragma unroll
    for (int s = 0; s < 4; s++) {
        aBase[s] = (unsigned)__cvta_generic_to_shared(As[s]);
        bBase[s] = (unsigned)__cvta_generic_to_shared(Bs[s]);
    }

    float acc[4][4][4];
#pragma unroll
    for (int i = 0; i < 4; i++)
#pragma unroll
        for (int j = 0; j < 4; j++)
#pragma unroll
            for (int r = 0; r < 4; r++) acc[i][j][r] = 0.f;

    const int KT = K >> 5;

    {
        unsigned* as0 = As[0]; unsigned* bs0 = Bs[0];
        cp_async16(as0 + sRow * SWS + sOff,     Ap);
        cp_async16(as0 + sRow * SWS + sOff + 4, Ap + 8);
        cp_async16(bs0 + sRow * SWS + sOff,     Bp);
        cp_async16(bs0 + sRow * SWS + sOff + 4, Bp + 8);
        unsigned* as1 = As[1]; unsigned* bs1 = Bs[1];
        cp_async16(as1 + sRow * SWS + sOff,     Ap + 32);
        cp_async16(as1 + sRow * SWS + sOff + 4, Ap + 40);
        cp_async16(bs1 + sRow * SWS + sOff,     Bp + 32);
        cp_async16(bs1 + sRow * SWS + sOff + 4, Bp + 40);
    }
    CP_COMMIT();

    for (int kt2 = 0; kt2 < KT; kt2 += 2) {
        CP_WAIT0();
        __syncthreads();

        if (kt2 + 2 < KT) {
            int stA = (kt2 + 2) & 3, stB = (kt2 + 3) & 3;
            const __half* apA = Ap + (size_t)(kt2 + 2) * 32;
            const __half* bpA = Bp + (size_t)(kt2 + 2) * 32;
            unsigned* as = As[stA]; unsigned* bs = Bs[stA];
            cp_async16(as + sRow * SWS + sOff,     apA);
            cp_async16(as + sRow * SWS + sOff + 4, apA + 8);
            cp_async16(bs + sRow * SWS + sOff,     bpA);
            cp_async16(bs + sRow * SWS + sOff + 4, bpA + 8);
            unsigned* as2 = As[stB]; unsigned* bs2 = Bs[stB];
            cp_async16(as2 + sRow * SWS + sOff,     apA + 32);
            cp_async16(as2 + sRow * SWS + sOff + 4, apA + 40);
            cp_async16(bs2 + sRow * SWS + sOff,     bpA + 32);
            cp_async16(bs2 + sRow * SWS + sOff + 4, bpA + 40);
            CP_COMMIT();
        }

#pragma unroll
        for (int sub = 0; sub < 2; sub++) {
            const unsigned ab = aBase[(kt2 + sub) & 3];
            const unsigned bb = bBase[(kt2 + sub) & 3];
#pragma unroll
            for (int ko = 0; ko < 16; ko += 8) {
                unsigned af[4][4], bf[4][2];
#pragma unroll
                for (int mi = 0; mi < 4; mi++)
                    ldsm4(af[mi], ab + (((mi * 16 + arS) * SWS + ko + acS) << 2));
#pragma unroll
                for (int ni = 0; ni < 4; ni++)
                    ldsm2(bf[ni], bb + (((ni * 8 + brS) * SWS + ko + bcS) << 2));
#pragma unroll
                for (int mi = 0; mi < 4; mi++)
#pragma unroll
                    for (int ni = 0; ni < 4; ni++)
                        mma16(acc[mi][ni], af[mi], bf[ni]);
            }
        }
    }

    const float scale = 0.051031036307982884f;   // 1/sqrt(384)
#pragma unroll
    for (int mi = 0; mi < 4; mi++) {
        int row0 = bm + warpM * 64 + mi * 16 + gg;
        float sn[2], cs[2];
        if (flags == 2) {
            float2 rc0 = rope[row0 & 511];
            float2 rc1 = rope[(row0 + 8) & 511];
            cs[0] = rc0.x; sn[0] = rc0.y;
            cs[1] = rc1.x; sn[1] = rc1.y;
        }
#pragma unroll
        for (int ni = 0; ni < 4; ni++) {
            int col = bn + warpN * 32 + ni * 8 + qq * 2;
            float b0 = bias[col], b1 = bias[col + 1];
#pragma unroll
            for (int half = 0; half < 2; half++) {
                int row = row0 + half * 8;
                float xr = acc[mi][ni][half * 2 + 0] + b0;
                float xi = acc[mi][ni][half * 2 + 1] + b1;
                if (flags == 2) {
                    int mat = col / Cn;
                    if (mat < 2) {
                        float nr = cs[half] * xr - sn[half] * xi;
                        float ni2 = sn[half] * xr + cs[half] * xi;
                        xr = nr; xi = ni2;
                    }
                    int local = col - mat * Cn;
                    int h = local >> 6, d = local & 63;
                    int bbv = row >> 9, t = row & 511;
                    if (mat == 0) {
                        __half2 hv = __floats2half2_rn(xr * scale, xi * scale);
                        *(__half2*)(oq + ((size_t)(bbv * Hn + h) * Tn + t) * HDn + d) = hv;
                    } else if (mat == 1) {
                        __half2 hv = __floats2half2_rn(xr, xi);
                        *(__half2*)(ok + ((size_t)(bbv * Hn + h) * Tn + t) * HDn + d) = hv;
                    } else {
                        size_t vb = ((size_t)(bbv * Hn + h) * HDn + d) * Tn + t;
                        ov[vb]      = __float2half(xr);
                        ov[vb + Tn] = __float2half(xi);
                    }
                } else {
                    if (flags == 1) { xr = fmaxf(xr, 0.f); xi = fmaxf(xi, 0.f); }
                    __half2* p = (__half2*)(Cout16 + (size_t)row * N + col);
                    *p = __floats2half2_rn(xr, xi);
                }
            }
        }
    }
}

// ---------------- fp16 causal flash attention: 128q tile, 64-key smem stages ------
__global__ __launch_bounds__(256) void attn_mma(
    const __half* __restrict__ q, const __half* __restrict__ k,
    const __half* __restrict__ v, __half* __restrict__ o)
{
    __shared__ __align__(16) unsigned sm[ATOT];

    const int bh = blockIdx.y;
    const int qt = gridDim.x - 1 - blockIdx.x;   // long blocks first
    const int tid = threadIdx.x;
    const int warp = tid >> 5, lane = tid & 31;
    const int gg = lane >> 2, qq = lane & 3;
    const size_t base = (size_t)bh * Tn * HDn;
    const int q0 = qt * 128;
    const int ktiles = 2 * qt + 2;               // 64-key tiles

    const int lrS = lane & 7;
    const int lcS = ((lane >> 3) & 1) * 4;

    // prefetch KV tile 0 (64 keys)
    {
        unsigned* kd = sm + AK0;
        unsigned* vd = sm + AV0;
#pragma unroll
        for (int i = 0; i < 2; i++) {
            int idx = i * 256 + tid;
            int r = idx >> 3, seg = idx & 7;
            cp_async16(kd + r * ASTK + seg * 4, k + base + (size_t)r * 64 + seg * 8);
            cp_async16(vd + r * ASTV + seg * 4, v + base + (size_t)r * Tn + seg * 8);
        }
        CP_COMMIT();
    }

    unsigned qf[4][4];
    {
        const __half* q0p = q + base + (size_t)(q0 + warp * 16 + gg) * 64;
        const __half* q1p = q0p + 8 * 64;
#pragma unroll
        for (int ks = 0; ks < 4; ks++) {
            qf[ks][0] = *(const unsigned*)(q0p + ks * 16 + 2 * qq);
            qf[ks][1] = *(const unsigned*)(q1p + ks * 16 + 2 * qq);
            qf[ks][2] = *(const unsigned*)(q0p + ks * 16 + 2 * qq + 8);
            qf[ks][3] = *(const unsigned*)(q1p + ks * 16 + 2 * qq + 8);
        }
    }
    CP_WAIT0();
    __syncthreads();

    float oacc[8][4];
#pragma unroll
    for (int i = 0; i < 8; i++)
#pragma unroll
        for (int r = 0; r < 4; r++) oacc[i][r] = 0.f;
    float m0 = -INFINITY, m1 = -INFINITY, l0 = 0.f, l1 = 0.f;

    const int row0g = q0 + warp * 16 + gg;
    const int row1g = row0g + 8;

    for (int kt = 0; kt < ktiles; kt++) {
        const unsigned* Ks = sm + ((kt & 1) ? AK1 : AK0);
        const unsigned* Vs = sm + ((kt & 1) ? AV1 : AV0);

        if (kt + 1 < ktiles) {
            unsigned* kd = sm + (((kt + 1) & 1) ? AK1 : AK0);
            unsigned* vd = sm + (((kt + 1) & 1) ? AV1 : AV0);
            const int nb = (kt + 1) * 64;
#pragma unroll
            for (int i = 0; i < 2; i++) {
                int idx = i * 256 + tid;
                int r = idx >> 3, seg = idx & 7;
                cp_async16(kd + r * ASTK + seg * 4,
                           k + base + (size_t)(nb + r) * 64 + seg * 8);
                cp_async16(vd + r * ASTV + seg * 4,
                           v + base + (size_t)r * Tn + nb + seg * 8);
            }
            CP_COMMIT();
        }

        const unsigned vsBase = (unsigned)__cvta_generic_to_shared(Vs);

        // two 32-key compute subtiles per 64-key stage
#pragma unroll
        for (int sub = 0; sub < 2; sub++) {
            const int kbase = kt * 64 + sub * 32;
            const unsigned ksBase = (unsigned)__cvta_generic_to_shared(Ks + sub * 32 * ASTK);
            const int vcol = sub * 16;

            float s[4][4];
#pragma unroll
            for (int nt = 0; nt < 4; nt++)
#pragma unroll
                for (int r = 0; r < 4; r++) s[nt][r] = 0.f;
#pragma unroll
            for (int ks = 0; ks < 4; ks++) {
                unsigned bf[4][2];
#pragma unroll
                for (int nt = 0; nt < 4; nt++)
                    ldsm2(bf[nt], ksBase + (((nt * 8 + lrS) * ASTK + ks * 8 + lcS) << 2));
#pragma unroll
                for (int nt = 0; nt < 4; nt++) mma16(s[nt], qf[ks], bf[nt]);
            }

            if (kt >= 2 * qt) {
#pragma unroll
                for (int nt = 0; nt < 4; nt++) {
                    int c0 = kbase + nt * 8 + 2 * qq;
                    if (c0 > row0g)     s[nt][0] = -1e30f;
                    if (c0 + 1 > row0g) s[nt][1] = -1e30f;
                    if (c0 > row1g)     s[nt][2] = -1e30f;
                    if (c0 + 1 > row1g) s[nt][3] = -1e30f;
                }
            }

            float rm0 = -1e30f, rm1 = -1e30f;
#pragma unroll
            for (int nt = 0; nt < 4; nt++) {
                rm0 = fmaxf(rm0, fmaxf(s[nt][0], s[nt][1]));
                rm1 = fmaxf(rm1, fmaxf(s[nt][2], s[nt][3]));
            }
            rm0 = fmaxf(rm0, __shfl_xor_sync(0xffffffffu, rm0, 1));
            rm0 = fmaxf(rm0, __shfl_xor_sync(0xffffffffu, rm0, 2));
            rm1 = fmaxf(rm1, __shfl_xor_sync(0xffffffffu, rm1, 1));
            rm1 = fmaxf(rm1, __shfl_xor_sync(0xffffffffu, rm1, 2));
            float nm0 = fmaxf(m0, rm0), nm1 = fmaxf(m1, rm1);
            float corr0 = __expf(m0 - nm0), corr1 = __expf(m1 - nm1);
            float rs0 = 0.f, rs1 = 0.f;
#pragma unroll
            for (int nt = 0; nt < 4; nt++) {
                s[nt][0] = __expf(s[nt][0] - nm0);
                s[nt][1] = __expf(s[nt][1] - nm0);
                s[nt][2] = __expf(s[nt][2] - nm1);
                s[nt][3] = __expf(s[nt][3] - nm1);
                rs0 += s[nt][0] + s[nt][1];
                rs1 += s[nt][2] + s[nt][3];
            }
            rs0 += __shfl_xor_sync(0xffffffffu, rs0, 1);
            rs0 += __shfl_xor_sync(0xffffffffu, rs0, 2);
            rs1 += __shfl_xor_sync(0xffffffffu, rs1, 1);
            rs1 += __shfl_xor_sync(0xffffffffu, rs1, 2);
            l0 = l0 * corr0 + rs0;
            l1 = l1 * corr1 + rs1;
            m0 = nm0; m1 = nm1;
#pragma unroll
            for (int nt = 0; nt < 8; nt++) {
                oacc[nt][0] *= corr0; oacc[nt][1] *= corr0;
                oacc[nt][2] *= corr1; oacc[nt][3] *= corr1;
            }

            unsigned pa[2][4];
            pa[0][0] = h2u(s[0][0], s[0][1]);
            pa[0][1] = h2u(s[0][2], s[0][3]);
            pa[0][2] = h2u(s[1][0], s[1][1]);
            pa[0][3] = h2u(s[1][2], s[1][3]);
            pa[1][0] = h2u(s[2][0], s[2][1]);
            pa[1][1] = h2u(s[2][2], s[2][3]);
            pa[1][2] = h2u(s[3][0], s[3][1]);
            pa[1][3] = h2u(s[3][2], s[3][3]);

#pragma unroll
            for (int ks = 0; ks < 2; ks++) {
#pragma unroll
                for (int nt = 0; nt < 8; nt++) {
                    unsigned bf2[2];
                    ldsm2(bf2, vsBase + (((nt * 8 + lrS) * ASTV + vcol + ks * 8 + lcS) << 2));
                    mma16(oacc[nt], pa[ks], bf2);
                }
            }
        }

        if (kt + 1 < ktiles) {
            CP_WAIT0();
            __syncthreads();
        }
    }

    const float inv0 = 1.f / l0, inv1 = 1.f / l1;
    const int b = bh / Hn, h = bh % Hn;
    __half* p0 = o + ((size_t)(b * Tn + row0g)) * Cn + h * 64;
    __half* p1 = o + ((size_t)(b * Tn + row1g)) * Cn + h * 64;
#pragma unroll
    for (int nt = 0; nt < 8; nt++) {
        *(__half2*)(p0 + nt * 8 + 2 * qq) = __floats2half2_rn(oacc[nt][0] * inv0, oacc[nt][1] * inv0);
        *(__half2*)(p1 + nt * 8 + 2 * qq) = __floats2half2_rn(oacc[nt][2] * inv1, oacc[nt][3] * inv1);
    }
}

// ---------------- fused residual + LayerNorm: y fp16, 2 rows/block ---------------
__global__ __launch_bounds__(256) void ln_res_k(
    const float* __restrict__ x, const __half* __restrict__ y,
    const float* __restrict__ g, const float* __restrict__ bb,
    float* __restrict__ out, __half* __restrict__ out16)
{
    __shared__ float red[8];
    const int half = threadIdx.x >> 7;
    const int tid = threadIdx.x & 127;
    const int row = blockIdx.x * 2 + half;
    const size_t base = (size_t)row * Cn;
    float v0 = x[base + tid]       + __half2float(y[base + tid]);
    float v1 = x[base + tid + 128] + __half2float(y[base + tid + 128]);
    float v2 = x[base + tid + 256] + __half2float(y[base + tid + 256]);

    float s = v0 + v1 + v2;
    for (int o = 16; o > 0; o >>= 1) s += __shfl_xor_sync(0xffffffffu, s, o);
    if ((tid & 31) == 0) red[half * 4 + (tid >> 5)] = s;
    __syncthreads();
    float mean = (red[half * 4] + red[half * 4 + 1] + red[half * 4 + 2] + red[half * 4 + 3]) * (1.f / Cn);
    __syncthreads();

    float d0 = v0 - mean, d1 = v1 - mean, d2 = v2 - mean;
    float sq = d0 * d0 + d1 * d1 + d2 * d2;
    for (int o = 16; o > 0; o >>= 1) sq += __shfl_xor_sync(0xffffffffu, sq, o);
    if ((tid & 31) == 0) red[half * 4 + (tid >> 5)] = sq;
    __syncthreads();
    float var = (red[half * 4] + red[half * 4 + 1] + red[half * 4 + 2] + red[half * 4 + 3]) * (1.f / Cn);
    float inv = rsqrtf(var + EPSn);

    float o0 = g[tid]       * d0 * inv + bb[tid];
    float o1 = g[tid + 128] * d1 * inv + bb[tid + 128];
    float o2 = g[tid + 256] * d2 * inv + bb[tid + 256];
    out[base + tid]       = o0;
    out[base + tid + 128] = o1;
    out[base + tid + 256] = o2;
    if (out16) {
        out16[base + tid]       = __float2half(o0);
        out16[base + tid + 128] = __float2half(o1);
        out16[base + tid + 256] = __float2half(o2);
    }
}

// ---------------- host orchestration ----------------
extern "C" void kernel_launch(void* const* d_in, const int* in_sizes, int n_in,
                              void* d_out, int out_size)
{
    (void)in_sizes; (void)n_in; (void)out_size;
    const float* x    = (const float*)d_in[0];
    const float* q1w  = (const float*)d_in[1];
    const float* q1b  = (const float*)d_in[2];
    const float* k1w  = (const float*)d_in[3];
    const float* k1b  = (const float*)d_in[4];
    const float* v1w  = (const float*)d_in[5];
    const float* v1b  = (const float*)d_in[6];
    const float* p1w  = (const float*)d_in[7];
    const float* p1b  = (const float*)d_in[8];
    const float* ln1g = (const float*)d_in[9];
    const float* ln1b = (const float*)d_in[10];
    const float* q2w  = (const float*)d_in[11];
    const float* q2b  = (const float*)d_in[12];
    const float* k2w  = (const float*)d_in[13];
    const float* k2b  = (const float*)d_in[14];
    const float* v2w  = (const float*)d_in[15];
    const float* v2b  = (const float*)d_in[16];
    const float* p2w  = (const float*)d_in[17];
    const float* p2b  = (const float*)d_in[18];
    const float* ln2g = (const float*)d_in[19];
    const float* ln2b = (const float*)d_in[20];
    const float* f1w  = (const float*)d_in[21];
    const float* f1b  = (const float*)d_in[22];
    const float* f2w  = (const float*)d_in[23];
    const float* f2b  = (const float*)d_in[24];
    const float* ln3g = (const float*)d_in[25];
    const float* ln3b = (const float*)d_in[26];
    float* out = (float*)d_out;

    __half *pwqkv1, *pwqkv2, *pwp1, *pwp2, *pwf1, *pwf2;
    __half *px16, *po16, *pr16, *ph16, *py16, *pq16, *pk16, *pv16t;
    float *pbqkv1, *pbqkv2, *pr1, *pr2;
    float2* prope;
    cudaGetSymbolAddress((void**)&pwqkv1, g_wqkv1);
    cudaGetSymbolAddress((void**)&pwqkv2, g_wqkv2);
    cudaGetSymbolAddress((void**)&pwp1, g_wp1);
    cudaGetSymbolAddress((void**)&pwp2, g_wp2);
    cudaGetSymbolAddress((void**)&pwf1, g_wf1t);
    cudaGetSymbolAddress((void**)&pwf2, g_wf2t);
    cudaGetSymbolAddress((void**)&px16, g_x16);
    cudaGetSymbolAddress((void**)&po16, g_o16);
    cudaGetSymbolAddress((void**)&pr16, g_r16);
    cudaGetSymbolAddress((void**)&ph16, g_h16);
    cudaGetSymbolAddress((void**)&py16, g_y16);
    cudaGetSymbolAddress((void**)&pq16, g_q16);
    cudaGetSymbolAddress((void**)&pk16, g_k16);
    cudaGetSymbolAddress((void**)&pv16t, g_v16t);
    cudaGetSymbolAddress((void**)&pbqkv1, g_bqkv1);
    cudaGetSymbolAddress((void**)&pbqkv2, g_bqkv2);
    cudaGetSymbolAddress((void**)&pr1, g_r1);
    cudaGetSymbolAddress((void**)&pr2, g_r2);
    cudaGetSymbolAddress((void**)&prope, g_rope);

    prep_all<<<(PTOT + 255) / 256, 256>>>(
        x, px16,
        q1w, k1w, v1w, pwqkv1,
        q2w, k2w, v2w, pwqkv2,
        p1w, pwp1, p2w, pwp2,
        f1w, pwf1, f2w, pwf2,
        q1b, k1b, v1b, pbqkv1,
        q2b, k2b, v2b, pbqkv2,
        prope);

    auto run_layer = [&](const float* xin_f32, const __half* xin_f16,
                         const __half* wqkv, const float* bqkv, const __half* wp,
                         const float* pb, const float* lng, const float* lnb,
                         float* rout, __half* rout16) {
        gemm_f16<<<dim3(3 * Cn / 128, BTn / 128), 256>>>(
            xin_f16, wqkv, bqkv, nullptr, BTn, 3 * Cn, Cn, 2, pq16, pk16, pv16t, prope);
        attn_mma<<<dim3(Tn / 128, Bn * Hn), 256>>>(pq16, pk16, pv16t, po16);
        gemm_f16<<<dim3(Cn / 128, BTn / 128), 256>>>(
            po16, wp, pb, py16, BTn, Cn, Cn, 0, nullptr, nullptr, nullptr, prope);
        ln_res_k<<<BTn / 2, 256>>>(xin_f32, py16, lng, lnb, rout, rout16);
    };

    run_layer(x,   px16, pwqkv1, pbqkv1, pwp1, p1b, ln1g, ln1b, pr1, pr16);
    run_layer(pr1, pr16, pwqkv2, pbqkv2, pwp2, p2b, ln2g, ln2b, pr2, pr16);

    gemm_f16<<<dim3(FFn / 128, BTn / 128), 256>>>(
        pr16, pwf1, f1b, ph16, BTn, FFn, Cn, 1, nullptr, nullptr, nullptr, prope);
    gemm_f16<<<dim3(Cn / 128, BTn / 128), 256>>>(
        ph16, pwf2, f2b, py16, BTn, Cn, FFn, 0, nullptr, nullptr, nullptr, prope);
    ln_res_k<<<BTn / 2, 256>>>(pr2, py16, ln3g, ln3b, out, nullptr);
}

// round 15
// speedup vs baseline: 1.5937x; 1.0082x over previous
#include <cuda_runtime.h>
#include <cuda_fp16.h>
#include <math.h>

#define Bn 64
#define Tn 512
#define Cn 384
#define Hn 6
#define HDn 64
#define FFn 1536
#define BTn (Bn*Tn)
#define EPSn 1e-5f

#define SWS 20    // gemm smem row stride (u32 words)

// fp16 attention smem (u32 word strides), 64-key stages
#define ASTK 36
#define ASTV 36
#define AK0 0
#define AV0 (64*ASTK)
#define AK1 (2*64*ASTK)
#define AV1 (3*64*ASTK)
#define ATOT (4*64*ASTK)

// ---------------- scratch ----------------
__device__ __half g_wqkv1[3*Cn*Cn];
__device__ __half g_wqkv2[3*Cn*Cn];
__device__ __half g_wp1[Cn*Cn];
__device__ __half g_wp2[Cn*Cn];
__device__ __half g_wf1t[FFn*Cn];
__device__ __half g_wf2t[Cn*FFn];
__device__ float  g_bqkv1[3*Cn];
__device__ float  g_bqkv2[3*Cn];
__device__ float2 g_rope[Tn];
__device__ __half g_x16[(size_t)BTn*Cn];
__device__ __half g_o16[(size_t)BTn*Cn];
__device__ __half g_r16[(size_t)BTn*Cn];
__device__ __half g_h16[(size_t)BTn*FFn];
__device__ __half g_y16[(size_t)BTn*Cn];
__device__ __half g_q16[(size_t)Bn*Hn*Tn*HDn];
__device__ __half g_k16[(size_t)Bn*Hn*Tn*HDn];
__device__ __half g_v16t[(size_t)Bn*Hn*HDn*Tn];
__device__ float g_r1[(size_t)BTn*Cn];
__device__ float g_r2[(size_t)BTn*Cn];

// ---------------- fused prep ----------------
#define SEG0 (BTn*Cn)
#define SEG1 (3*Cn*Cn)
#define SEG2 (3*Cn*Cn)
#define SEG3 (Cn*Cn)
#define SEG4 (Cn*Cn)
#define SEG5 (FFn*Cn)
#define SEG6 (Cn*FFn)
#define SEG7 (3*Cn)
#define SEG8 (3*Cn)
#define SEG9 (Tn)
#define PTOT (SEG0+SEG1+SEG2+SEG3+SEG4+SEG5+SEG6+SEG7+SEG8+SEG9)

__device__ __forceinline__ void pack_qkv_w(const float* qw, const float* kw,
                                           const float* vw, __half* o, int i) {
    int n = i / Cn, k = i % Cn;
    int mat = n / Cn, local = n % Cn;
    int h = local >> 6, d = local & 63;
    const float* w = (mat == 0) ? qw : (mat == 1) ? kw : vw;
    o[i] = __float2half(w[((size_t)h * Cn + k) * HDn + d]);
}
__device__ __forceinline__ void pack_wt(const float* w, __half* o, int N, int K, int i) {
    int n = i / K, k = i % K;
    o[i] = __float2half(w[(size_t)k * N + n]);
}

__global__ void prep_all(
    const float* __restrict__ x, __half* __restrict__ x16,
    const float* __restrict__ q1w, const float* __restrict__ k1w, const float* __restrict__ v1w,
    __half* __restrict__ wqkv1,
    const float* __restrict__ q2w, const float* __restrict__ k2w, const float* __restrict__ v2w,
    __half* __restrict__ wqkv2,
    const float* __restrict__ p1w, __half* __restrict__ wp1,
    const float* __restrict__ p2w, __half* __restrict__ wp2,
    const float* __restrict__ f1w, __half* __restrict__ wf1,
    const float* __restrict__ f2w, __half* __restrict__ wf2,
    const float* __restrict__ q1b, const float* __restrict__ k1b, const float* __restrict__ v1b,
    float* __restrict__ bqkv1,
    const float* __restrict__ q2b, const float* __restrict__ k2b, const float* __restrict__ v2b,
    float* __restrict__ bqkv2,
    float2* __restrict__ rope)
{
    int i = blockIdx.x * blockDim.x + threadIdx.x;
    if (i >= PTOT) return;
    if (i < SEG0) { x16[i] = __float2half(x[i]); return; }
    i -= SEG0;
    if (i < SEG1) { pack_qkv_w(q1w, k1w, v1w, wqkv1, i); return; }
    i -= SEG1;
    if (i < SEG2) { pack_qkv_w(q2w, k2w, v2w, wqkv2, i); return; }
    i -= SEG2;
    if (i < SEG3) { pack_wt(p1w, wp1, Cn, Cn, i); return; }
    i -= SEG3;
    if (i < SEG4) { pack_wt(p2w, wp2, Cn, Cn, i); return; }
    i -= SEG4;
    if (i < SEG5) { pack_wt(f1w, wf1, FFn, Cn, i); return; }
    i -= SEG5;
    if (i < SEG6) { pack_wt(f2w, wf2, Cn, FFn, i); return; }
    i -= SEG6;
    if (i < SEG7) {
        const float* b = (i < Cn) ? q1b : (i < 2 * Cn) ? k1b : v1b;
        bqkv1[i] = b[i % Cn]; return;
    }
    i -= SEG7;
    if (i < SEG8) {
        const float* b = (i < Cn) ? q2b : (i < 2 * Cn) ? k2b : v2b;
        bqkv2[i] = b[i % Cn]; return;
    }
    i -= SEG8;
    {
        float s, c;
        sincosf((float)i, &s, &c);
        rope[i] = make_float2(c, s);
    }
}

// ---------------- mma / ldmatrix / async helpers ----------------
__device__ __forceinline__ void mma16(float* d, const unsigned* a, const unsigned* b) {
    asm("mma.sync.aligned.m16n8k16.row.col.f32.f16.f16.f32 "
        "{%0,%1,%2,%3},{%4,%5,%6,%7},{%8,%9},{%0,%1,%2,%3};"
        : "+f"(d[0]), "+f"(d[1]), "+f"(d[2]), "+f"(d[3])
        : "r"(a[0]), "r"(a[1]), "r"(a[2]), "r"(a[3]), "r"(b[0]), "r"(b[1]));
}
__device__ __forceinline__ void ldsm4(unsigned* r, unsigned addr) {
    asm volatile("ldmatrix.sync.aligned.m8n8.x4.shared.b16 {%0,%1,%2,%3}, [%4];"
        : "=r"(r[0]), "=r"(r[1]), "=r"(r[2]), "=r"(r[3]) : "r"(addr));
}
__device__ __forceinline__ unsigned h2u(float a, float b) {
    __half2 h = __floats2half2_rn(a, b);
    return *(unsigned*)&h;
}
__device__ __forceinline__ void cp_async16(void* smem_dst, const void* gsrc) {
    unsigned saddr = (unsigned)__cvta_generic_to_shared(smem_dst);
    asm volatile("cp.async.ca.shared.global [%0], [%1], 16;\n" :: "r"(saddr), "l"(gsrc));
}
#define CP_COMMIT() asm volatile("cp.async.commit_group;\n" ::: "memory")
#define CP_WAIT0()  asm volatile("cp.async.wait_group 0;\n" ::: "memory")

// ---------------- fp16 GEMM: 4-stage pair-iterated, ldsm4-paired B ----------------
// flags: 0 = fp16 out (no relu); 1 = relu + fp16 out; 2 = qkv scatter fp16 (+rope)
__global__ __launch_bounds__(256) void gemm_f16(
    const __half* __restrict__ A, const __half* __restrict__ Bm,
    const float* __restrict__ bias,
    __half* __restrict__ Cout16,
    int M, int N, int K, int flags,
    __half* __restrict__ oq, __half* __restrict__ ok, __half* __restrict__ ov,
    const float2* __restrict__ rope)
{
    __shared__ __align__(16) unsigned As[4][128 * SWS];
    __shared__ __align__(16) unsigned Bs[4][128 * SWS];

    const int tid = threadIdx.x;
    const int lane = tid & 31, warp = tid >> 5;
    const int warpM = warp >> 2, warpN = warp & 3;
    const int bm = blockIdx.y * 128, bn = blockIdx.x * 128;
    const int qq = lane & 3, gg = lane >> 2;

    const int sRow = tid >> 1;
    const int sOff = (tid & 1) * 8;
    const __half* Ap = A + (size_t)(bm + sRow) * K + (tid & 1) * 16;
    const __half* Bp = Bm + (size_t)(bn + sRow) * K + (tid & 1) * 16;

    const int arS = warpM * 64 + (lane & 7) + ((lane >> 3) & 1) * 8;
    const int acS = (lane >> 4) * 4;
    // x4-paired B selectors: lanes 0-15 -> first n-8-tile, 16-31 -> second
    const int br4 = warpN * 32 + ((lane >> 4) << 3) + (lane & 7);
    const int bc4 = ((lane >> 3) & 1) * 4;

    unsigned aBase[4], bBase[4];
#pragma unroll
    for (int s = 0; s < 4; s++) {
        aBase[s] = (unsigned)__cvta_generic_to_shared(As[s]);
        bBase[s] = (unsigned)__cvta_generic_to_shared(Bs[s]);
    }

    float acc[4][4][4];
#pragma unroll
    for (int i = 0; i < 4; i++)
#pragma unroll
        for (int j = 0; j < 4; j++)
#pragma unroll
            for (int r = 0; r < 4; r++) acc[i][j][r] = 0.f;

    const int KT = K >> 5;

    {
        unsigned* as0 = As[0]; unsigned* bs0 = Bs[0];
        cp_async16(as0 + sRow * SWS + sOff,     Ap);
        cp_async16(as0 + sRow * SWS + sOff + 4, Ap + 8);
        cp_async16(bs0 + sRow * SWS + sOff,     Bp);
        cp_async16(bs0 + sRow * SWS + sOff + 4, Bp + 8);
        unsigned* as1 = As[1]; unsigned* bs1 = Bs[1];
        cp_async16(as1 + sRow * SWS + sOff,     Ap + 32);
        cp_async16(as1 + sRow * SWS + sOff + 4, Ap + 40);
        cp_async16(bs1 + sRow * SWS + sOff,     Bp + 32);
        cp_async16(bs1 + sRow * SWS + sOff + 4, Bp + 40);
    }
    CP_COMMIT();

    for (int kt2 = 0; kt2 < KT; kt2 += 2) {
        CP_WAIT0();
        __syncthreads();

        if (kt2 + 2 < KT) {
            int stA = (kt2 + 2) & 3, stB = (kt2 + 3) & 3;
            const __half* apA = Ap + (size_t)(kt2 + 2) * 32;
            const __half* bpA = Bp + (size_t)(kt2 + 2) * 32;
            unsigned* as = As[stA]; unsigned* bs = Bs[stA];
            cp_async16(as + sRow * SWS + sOff,     apA);
            cp_async16(as + sRow * SWS + sOff + 4, apA + 8);
            cp_async16(bs + sRow * SWS + sOff,     bpA);
            cp_async16(bs + sRow * SWS + sOff + 4, bpA + 8);
            unsigned* as2 = As[stB]; unsigned* bs2 = Bs[stB];
            cp_async16(as2 + sRow * SWS + sOff,     apA + 32);
            cp_async16(as2 + sRow * SWS + sOff + 4, apA + 40);
            cp_async16(bs2 + sRow * SWS + sOff,     bpA + 32);
            cp_async16(bs2 + sRow * SWS + sOff + 4, bpA + 40);
            CP_COMMIT();
        }

#pragma unroll
        for (int sub = 0; sub < 2; sub++) {
            const unsigned ab = aBase[(kt2 + sub) & 3];
            const unsigned bb = bBase[(kt2 + sub) & 3];
#pragma unroll
            for (int ko = 0; ko < 16; ko += 8) {
                unsigned af[4][4], bf4[2][4];
#pragma unroll
                for (int mi = 0; mi < 4; mi++)
                    ldsm4(af[mi], ab + (((mi * 16 + arS) * SWS + ko + acS) << 2));
#pragma unroll
                for (int np = 0; np < 2; np++)
                    ldsm4(bf4[np], bb + (((np * 16 + br4) * SWS + ko + bc4) << 2));
#pragma unroll
                for (int mi = 0; mi < 4; mi++)
#pragma unroll
                    for (int ni = 0; ni < 4; ni++)
                        mma16(acc[mi][ni], af[mi], &bf4[ni >> 1][(ni & 1) * 2]);
            }
        }
    }

    const float scale = 0.051031036307982884f;   // 1/sqrt(384)
#pragma unroll
    for (int mi = 0; mi < 4; mi++) {
        int row0 = bm + warpM * 64 + mi * 16 + gg;
        float sn[2], cs[2];
        if (flags == 2) {
            float2 rc0 = rope[row0 & 511];
            float2 rc1 = rope[(row0 + 8) & 511];
            cs[0] = rc0.x; sn[0] = rc0.y;
            cs[1] = rc1.x; sn[1] = rc1.y;
        }
#pragma unroll
        for (int ni = 0; ni < 4; ni++) {
            int col = bn + warpN * 32 + ni * 8 + qq * 2;
            float b0 = bias[col], b1 = bias[col + 1];
#pragma unroll
            for (int half = 0; half < 2; half++) {
                int row = row0 + half * 8;
                float xr = acc[mi][ni][half * 2 + 0] + b0;
                float xi = acc[mi][ni][half * 2 + 1] + b1;
                if (flags == 2) {
                    int mat = col / Cn;
                    if (mat < 2) {
                        float nr = cs[half] * xr - sn[half] * xi;
                        float ni2 = sn[half] * xr + cs[half] * xi;
                        xr = nr; xi = ni2;
                    }
                    int local = col - mat * Cn;
                    int h = local >> 6, d = local & 63;
                    int bbv = row >> 9, t = row & 511;
                    if (mat == 0) {
                        __half2 hv = __floats2half2_rn(xr * scale, xi * scale);
                        *(__half2*)(oq + ((size_t)(bbv * Hn + h) * Tn + t) * HDn + d) = hv;
                    } else if (mat == 1) {
                        __half2 hv = __floats2half2_rn(xr, xi);
                        *(__half2*)(ok + ((size_t)(bbv * Hn + h) * Tn + t) * HDn + d) = hv;
                    } else {
                        size_t vb = ((size_t)(bbv * Hn + h) * HDn + d) * Tn + t;
                        ov[vb]      = __float2half(xr);
                        ov[vb + Tn] = __float2half(xi);
                    }
                } else {
                    if (flags == 1) { xr = fmaxf(xr, 0.f); xi = fmaxf(xi, 0.f); }
                    __half2* p = (__half2*)(Cout16 + (size_t)row * N + col);
                    *p = __floats2half2_rn(xr, xi);
                }
            }
        }
    }
}

// ---------------- fp16 causal flash attention: 128q tile, 64-key stages, x4 loads -
__global__ __launch_bounds__(256) void attn_mma(
    const __half* __restrict__ q, const __half* __restrict__ k,
    const __half* __restrict__ v, __half* __restrict__ o)
{
    __shared__ __align__(16) unsigned sm[ATOT];

    const int bh = blockIdx.y;
    const int qt = gridDim.x - 1 - blockIdx.x;   // long blocks first
    const int tid = threadIdx.x;
    const int warp = tid >> 5, lane = tid & 31;
    const int gg = lane >> 2, qq = lane & 3;
    const size_t base = (size_t)bh * Tn * HDn;
    const int q0 = qt * 128;
    const int ktiles = 2 * qt + 2;               // 64-key tiles

    // x4 selectors (first/second 8-row group by lane>>4)
    const int a4r = ((lane >> 4) << 3) + (lane & 7);
    const int a4c = ((lane >> 3) & 1) * 4;

    // prefetch KV tile 0 (64 keys)
    {
        unsigned* kd = sm + AK0;
        unsigned* vd = sm + AV0;
#pragma unroll
        for (int i = 0; i < 2; i++) {
            int idx = i * 256 + tid;
            int r = idx >> 3, seg = idx & 7;
            cp_async16(kd + r * ASTK + seg * 4, k + base + (size_t)r * 64 + seg * 8);
            cp_async16(vd + r * ASTV + seg * 4, v + base + (size_t)r * Tn + seg * 8);
        }
        CP_COMMIT();
    }

    unsigned qf[4][4];
    {
        const __half* q0p = q + base + (size_t)(q0 + warp * 16 + gg) * 64;
        const __half* q1p = q0p + 8 * 64;
#pragma unroll
        for (int ks = 0; ks < 4; ks++) {
            qf[ks][0] = *(const unsigned*)(q0p + ks * 16 + 2 * qq);
            qf[ks][1] = *(const unsigned*)(q1p + ks * 16 + 2 * qq);
            qf[ks][2] = *(const unsigned*)(q0p + ks * 16 + 2 * qq + 8);
            qf[ks][3] = *(const unsigned*)(q1p + ks * 16 + 2 * qq + 8);
        }
    }
    CP_WAIT0();
    __syncthreads();

    float oacc[8][4];
#pragma unroll
    for (int i = 0; i < 8; i++)
#pragma unroll
        for (int r = 0; r < 4; r++) oacc[i][r] = 0.f;
    float m0 = -INFINITY, m1 = -INFINITY, l0 = 0.f, l1 = 0.f;

    const int row0g = q0 + warp * 16 + gg;
    const int row1g = row0g + 8;

    for (int kt = 0; kt < ktiles; kt++) {
        const unsigned* Ks = sm + ((kt & 1) ? AK1 : AK0);
        const unsigned* Vs = sm + ((kt & 1) ? AV1 : AV0);

        if (kt + 1 < ktiles) {
            unsigned* kd = sm + (((kt + 1) & 1) ? AK1 : AK0);
            unsigned* vd = sm + (((kt + 1) & 1) ? AV1 : AV0);
            const int nb = (kt + 1) * 64;
#pragma unroll
            for (int i = 0; i < 2; i++) {
                int idx = i * 256 + tid;
                int r = idx >> 3, seg = idx & 7;
                cp_async16(kd + r * ASTK + seg * 4,
                           k + base + (size_t)(nb + r) * 64 + seg * 8);
                cp_async16(vd + r * ASTV + seg * 4,
                           v + base + (size_t)r * Tn + nb + seg * 8);
            }
            CP_COMMIT();
        }

        const unsigned vsBase = (unsigned)__cvta_generic_to_shared(Vs);

#pragma unroll
        for (int sub = 0; sub < 2; sub++) {
            const int kbase = kt * 64 + sub * 32;
            const unsigned ksBase = (unsigned)__cvta_generic_to_shared(Ks + sub * 32 * ASTK);
            const int vcol = sub * 16;

            float s[4][4];
#pragma unroll
            for (int nt = 0; nt < 4; nt++)
#pragma unroll
                for (int r = 0; r < 4; r++) s[nt][r] = 0.f;
#pragma unroll
            for (int ks = 0; ks < 4; ks++) {
                unsigned bk[2][4];
#pragma unroll
                for (int np = 0; np < 2; np++)
                    ldsm4(bk[np], ksBase + (((np * 16 + a4r) * ASTK + ks * 8 + a4c) << 2));
#pragma unroll
                for (int nt = 0; nt < 4; nt++)
                    mma16(s[nt], qf[ks], &bk[nt >> 1][(nt & 1) * 2]);
            }

            if (kt >= 2 * qt) {
#pragma unroll
                for (int nt = 0; nt < 4; nt++) {
                    int c0 = kbase + nt * 8 + 2 * qq;
                    if (c0 > row0g)     s[nt][0] = -1e30f;
                    if (c0 + 1 > row0g) s[nt][1] = -1e30f;
                    if (c0 > row1g)     s[nt][2] = -1e30f;
                    if (c0 + 1 > row1g) s[nt][3] = -1e30f;
                }
            }

            float rm0 = -1e30f, rm1 = -1e30f;
#pragma unroll
            for (int nt = 0; nt < 4; nt++) {
                rm0 = fmaxf(rm0, fmaxf(s[nt][0], s[nt][1]));
                rm1 = fmaxf(rm1, fmaxf(s[nt][2], s[nt][3]));
            }
            rm0 = fmaxf(rm0, __shfl_xor_sync(0xffffffffu, rm0, 1));
            rm0 = fmaxf(rm0, __shfl_xor_sync(0xffffffffu, rm0, 2));
            rm1 = fmaxf(rm1, __shfl_xor_sync(0xffffffffu, rm1, 1));
            rm1 = fmaxf(rm1, __shfl_xor_sync(0xffffffffu, rm1, 2));
            float nm0 = fmaxf(m0, rm0), nm1 = fmaxf(m1, rm1);
            float corr0 = __expf(m0 - nm0), corr1 = __expf(m1 - nm1);
            float rs0 = 0.f, rs1 = 0.f;
#pragma unroll
            for (int nt = 0; nt < 4; nt++) {
                s[nt][0] = __expf(s[nt][0] - nm0);
                s[nt][1] = __expf(s[nt][1] - nm0);
                s[nt][2] = __expf(s[nt][2] - nm1);
                s[nt][3] = __expf(s[nt][3] - nm1);
                rs0 += s[nt][0] + s[nt][1];
                rs1 += s[nt][2] + s[nt][3];
            }
            rs0 += __shfl_xor_sync(0xffffffffu, rs0, 1);
            rs0 += __shfl_xor_sync(0xffffffffu, rs0, 2);
            rs1 += __shfl_xor_sync(0xffffffffu, rs1, 1);
            rs1 += __shfl_xor_sync(0xffffffffu, rs1, 2);
            l0 = l0 * corr0 + rs0;
            l1 = l1 * corr1 + rs1;
            m0 = nm0; m1 = nm1;
#pragma unroll
            for (int nt = 0; nt < 8; nt++) {
                oacc[nt][0] *= corr0; oacc[nt][1] *= corr0;
                oacc[nt][2] *= corr1; oacc[nt][3] *= corr1;
            }

            unsigned pa[2][4];
            pa[0][0] = h2u(s[0][0], s[0][1]);
            pa[0][1] = h2u(s[0][2], s[0][3]);
            pa[0][2] = h2u(s[1][0], s[1][1]);
            pa[0][3] = h2u(s[1][2], s[1][3]);
            pa[1][0] = h2u(s[2][0], s[2][1]);
            pa[1][1] = h2u(s[2][2], s[2][3]);
            pa[1][2] = h2u(s[3][0], s[3][1]);
            pa[1][3] = h2u(s[3][2], s[3][3]);

#pragma unroll
            for (int ks = 0; ks < 2; ks++) {
                unsigned bv[4][4];
#pragma unroll
                for (int np = 0; np < 4; np++)
                    ldsm4(bv[np], vsBase + (((np * 16 + a4r) * ASTV + vcol + ks * 8 + a4c) << 2));
#pragma unroll
                for (int nt = 0; nt < 8; nt++)
                    mma16(oacc[nt], pa[ks], &bv[nt >> 1][(nt & 1) * 2]);
            }
        }

        if (kt + 1 < ktiles) {
            CP_WAIT0();
            __syncthreads();
        }
    }

    const float inv0 = 1.f / l0, inv1 = 1.f / l1;
    const int b = bh / Hn, h = bh % Hn;
    __half* p0 = o + ((size_t)(b * Tn + row0g)) * Cn + h * 64;
    __half* p1 = o + ((size_t)(b * Tn + row1g)) * Cn + h * 64;
#pragma unroll
    for (int nt = 0; nt < 8; nt++) {
        *(__half2*)(p0 + nt * 8 + 2 * qq) = __floats2half2_rn(oacc[nt][0] * inv0, oacc[nt][1] * inv0);
        *(__half2*)(p1 + nt * 8 + 2 * qq) = __floats2half2_rn(oacc[nt][2] * inv1, oacc[nt][3] * inv1);
    }
}

// ---------------- fused residual + LayerNorm: y fp16, 2 rows/block ---------------
__global__ __launch_bounds__(256) void ln_res_k(
    const float* __restrict__ x, const __half* __restrict__ y,
    const float* __restrict__ g, const float* __restrict__ bb,
    float* __restrict__ out, __half* __restrict__ out16)
{
    __shared__ float red[8];
    const int half = threadIdx.x >> 7;
    const int tid = threadIdx.x & 127;
    const int row = blockIdx.x * 2 + half;
    const size_t base = (size_t)row * Cn;
    float v0 = x[base + tid]       + __half2float(y[base + tid]);
    float v1 = x[base + tid + 128] + __half2float(y[base + tid + 128]);
    float v2 = x[base + tid + 256] + __half2float(y[base + tid + 256]);

    float s = v0 + v1 + v2;
    for (int o = 16; o > 0; o >>= 1) s += __shfl_xor_sync(0xffffffffu, s, o);
    if ((tid & 31) == 0) red[half * 4 + (tid >> 5)] = s;
    __syncthreads();
    float mean = (red[half * 4] + red[half * 4 + 1] + red[half * 4 + 2] + red[half * 4 + 3]) * (1.f / Cn);
    __syncthreads();

    float d0 = v0 - mean, d1 = v1 - mean, d2 = v2 - mean;
    float sq = d0 * d0 + d1 * d1 + d2 * d2;
    for (int o = 16; o > 0; o >>= 1) sq += __shfl_xor_sync(0xffffffffu, sq, o);
    if ((tid & 31) == 0) red[half * 4 + (tid >> 5)] = sq;
    __syncthreads();
    float var = (red[half * 4] + red[half * 4 + 1] + red[half * 4 + 2] + red[half * 4 + 3]) * (1.f / Cn);
    float inv = rsqrtf(var + EPSn);

    float o0 = g[tid]       * d0 * inv + bb[tid];
    float o1 = g[tid + 128] * d1 * inv + bb[tid + 128];
    float o2 = g[tid + 256] * d2 * inv + bb[tid + 256];
    out[base + tid]       = o0;
    out[base + tid + 128] = o1;
    out[base + tid + 256] = o2;
    if (out16) {
        out16[base + tid]       = __float2half(o0);
        out16[base + tid + 128] = __float2half(o1);
        out16[base + tid + 256] = __float2half(o2);
    }
}

// ---------------- host orchestration ----------------
extern "C" void kernel_launch(void* const* d_in, const int* in_sizes, int n_in,
                              void* d_out, int out_size)
{
    (void)in_sizes; (void)n_in; (void)out_size;
    const float* x    = (const float*)d_in[0];
    const float* q1w  = (const float*)d_in[1];
    const float* q1b  = (const float*)d_in[2];
    const float* k1w  = (const float*)d_in[3];
    const float* k1b  = (const float*)d_in[4];
    const float* v1w  = (const float*)d_in[5];
    const float* v1b  = (const float*)d_in[6];
    const float* p1w  = (const float*)d_in[7];
    const float* p1b  = (const float*)d_in[8];
    const float* ln1g = (const float*)d_in[9];
    const float* ln1b = (const float*)d_in[10];
    const float* q2w  = (const float*)d_in[11];
    const float* q2b  = (const float*)d_in[12];
    const float* k2w  = (const float*)d_in[13];
    const float* k2b  = (const float*)d_in[14];
    const float* v2w  = (const float*)d_in[15];
    const float* v2b  = (const float*)d_in[16];
    const float* p2w  = (const float*)d_in[17];
    const float* p2b  = (const float*)d_in[18];
    const float* ln2g = (const float*)d_in[19];
    const float* ln2b = (const float*)d_in[20];
    const float* f1w  = (const float*)d_in[21];
    const float* f1b  = (const float*)d_in[22];
    const float* f2w  = (const float*)d_in[23];
    const float* f2b  = (const float*)d_in[24];
    const float* ln3g = (const float*)d_in[25];
    const float* ln3b = (const float*)d_in[26];
    float* out = (float*)d_out;

    __half *pwqkv1, *pwqkv2, *pwp1, *pwp2, *pwf1, *pwf2;
    __half *px16, *po16, *pr16, *ph16, *py16, *pq16, *pk16, *pv16t;
    float *pbqkv1, *pbqkv2, *pr1, *pr2;
    float2* prope;
    cudaGetSymbolAddress((void**)&pwqkv1, g_wqkv1);
    cudaGetSymbolAddress((void**)&pwqkv2, g_wqkv2);
    cudaGetSymbolAddress((void**)&pwp1, g_wp1);
    cudaGetSymbolAddress((void**)&pwp2, g_wp2);
    cudaGetSymbolAddress((void**)&pwf1, g_wf1t);
    cudaGetSymbolAddress((void**)&pwf2, g_wf2t);
    cudaGetSymbolAddress((void**)&px16, g_x16);
    cudaGetSymbolAddress((void**)&po16, g_o16);
    cudaGetSymbolAddress((void**)&pr16, g_r16);
    cudaGetSymbolAddress((void**)&ph16, g_h16);
    cudaGetSymbolAddress((void**)&py16, g_y16);
    cudaGetSymbolAddress((void**)&pq16, g_q16);
    cudaGetSymbolAddress((void**)&pk16, g_k16);
    cudaGetSymbolAddress((void**)&pv16t, g_v16t);
    cudaGetSymbolAddress((void**)&pbqkv1, g_bqkv1);
    cudaGetSymbolAddress((void**)&pbqkv2, g_bqkv2);
    cudaGetSymbolAddress((void**)&pr1, g_r1);
    cudaGetSymbolAddress((void**)&pr2, g_r2);
    cudaGetSymbolAddress((void**)&prope, g_rope);

    prep_all<<<(PTOT + 255) / 256, 256>>>(
        x, px16,
        q1w, k1w, v1w, pwqkv1,
        q2w, k2w, v2w, pwqkv2,
        p1w, pwp1, p2w, pwp2,
        f1w, pwf1, f2w, pwf2,
        q1b, k1b, v1b, pbqkv1,
        q2b, k2b, v2b, pbqkv2,
        prope);

    auto run_layer = [&](const float* xin_f32, const __half* xin_f16,
                         const __half* wqkv, const float* bqkv, const __half* wp,
                         const float* pb, const float* lng, const float* lnb,
                         float* rout, __half* rout16) {
        gemm_f16<<<dim3(3 * Cn / 128, BTn / 128), 256>>>(
            xin_f16, wqkv, bqkv, nullptr, BTn, 3 * Cn, Cn, 2, pq16, pk16, pv16t, prope);
        attn_mma<<<dim3(Tn / 128, Bn * Hn), 256>>>(pq16, pk16, pv16t, po16);
        gemm_f16<<<dim3(Cn / 128, BTn / 128), 256>>>(
            po16, wp, pb, py16, BTn, Cn, Cn, 0, nullptr, nullptr, nullptr, prope);
        ln_res_k<<<BTn / 2, 256>>>(xin_f32, py16, lng, lnb, rout, rout16);
    };

    run_layer(x,   px16, pwqkv1, pbqkv1, pwp1, p1b, ln1g, ln1b, pr1, pr16);
    run_layer(pr1, pr16, pwqkv2, pbqkv2, pwp2, p2b, ln2g, ln2b, pr2, pr16);

    gemm_f16<<<dim3(FFn / 128, BTn / 128), 256>>>(
        pr16, pwf1, f1b, ph16, BTn, FFn, Cn, 1, nullptr, nullptr, nullptr, prope);
    gemm_f16<<<dim3(Cn / 128, BTn / 128), 256>>>(
        ph16, pwf2, f2b, py16, BTn, Cn, FFn, 0, nullptr, nullptr, nullptr, prope);
    ln_res_k<<<BTn / 2, 256>>>(pr2, py16, ln3g, ln3b, out, nullptr);
}

// round 16
// speedup vs baseline: 1.6139x; 1.0127x over previous
#include <cuda_runtime.h>
#include <cuda_fp16.h>
#include <math.h>

#define Bn 64
#define Tn 512
#define Cn 384
#define Hn 6
#define HDn 64
#define FFn 1536
#define BTn (Bn*Tn)
#define EPSn 1e-5f

#define SWS 20    // gemm smem row stride (u32 words)

// fp16 attention smem (u32 word strides), 64-key stages
#define ASTK 36
#define ASTV 36
#define AK0 0
#define AV0 (64*ASTK)
#define AK1 (2*64*ASTK)
#define AV1 (3*64*ASTK)
#define ATOT (4*64*ASTK)

// ---------------- scratch ----------------
__device__ __half g_wqkv1[3*Cn*Cn];
__device__ __half g_wqkv2[3*Cn*Cn];
__device__ __half g_wp1[Cn*Cn];
__device__ __half g_wp2[Cn*Cn];
__device__ __half g_wf1t[FFn*Cn];
__device__ __half g_wf2t[Cn*FFn];
__device__ float  g_bqkv1[3*Cn];
__device__ float  g_bqkv2[3*Cn];
__device__ float2 g_rope[Tn];
__device__ __half g_x16[(size_t)BTn*Cn];
__device__ __half g_o16[(size_t)BTn*Cn];
__device__ __half g_r16[(size_t)BTn*Cn];   // fp16 residual chain
__device__ __half g_h16[(size_t)BTn*FFn];
__device__ __half g_y16[(size_t)BTn*Cn];
__device__ __half g_q16[(size_t)Bn*Hn*Tn*HDn];
__device__ __half g_k16[(size_t)Bn*Hn*Tn*HDn];
__device__ __half g_v16t[(size_t)Bn*Hn*HDn*Tn];

// ---------------- fused prep ----------------
#define SEG0 (BTn*Cn)
#define SEG1 (3*Cn*Cn)
#define SEG2 (3*Cn*Cn)
#define SEG3 (Cn*Cn)
#define SEG4 (Cn*Cn)
#define SEG5 (FFn*Cn)
#define SEG6 (Cn*FFn)
#define SEG7 (3*Cn)
#define SEG8 (3*Cn)
#define SEG9 (Tn)
#define PTOT (SEG0+SEG1+SEG2+SEG3+SEG4+SEG5+SEG6+SEG7+SEG8+SEG9)

__device__ __forceinline__ void pack_qkv_w(const float* qw, const float* kw,
                                           const float* vw, __half* o, int i) {
    int n = i / Cn, k = i % Cn;
    int mat = n / Cn, local = n % Cn;
    int h = local >> 6, d = local & 63;
    const float* w = (mat == 0) ? qw : (mat == 1) ? kw : vw;
    o[i] = __float2half(w[((size_t)h * Cn + k) * HDn + d]);
}
__device__ __forceinline__ void pack_wt(const float* w, __half* o, int N, int K, int i) {
    int n = i / K, k = i % K;
    o[i] = __float2half(w[(size_t)k * N + n]);
}

__global__ void prep_all(
    const float* __restrict__ x, __half* __restrict__ x16,
    const float* __restrict__ q1w, const float* __restrict__ k1w, const float* __restrict__ v1w,
    __half* __restrict__ wqkv1,
    const float* __restrict__ q2w, const float* __restrict__ k2w, const float* __restrict__ v2w,
    __half* __restrict__ wqkv2,
    const float* __restrict__ p1w, __half* __restrict__ wp1,
    const float* __restrict__ p2w, __half* __restrict__ wp2,
    const float* __restrict__ f1w, __half* __restrict__ wf1,
    const float* __restrict__ f2w, __half* __restrict__ wf2,
    const float* __restrict__ q1b, const float* __restrict__ k1b, const float* __restrict__ v1b,
    float* __restrict__ bqkv1,
    const float* __restrict__ q2b, const float* __restrict__ k2b, const float* __restrict__ v2b,
    float* __restrict__ bqkv2,
    float2* __restrict__ rope)
{
    int i = blockIdx.x * blockDim.x + threadIdx.x;
    if (i >= PTOT) return;
    if (i < SEG0) { x16[i] = __float2half(x[i]); return; }
    i -= SEG0;
    if (i < SEG1) { pack_qkv_w(q1w, k1w, v1w, wqkv1, i); return; }
    i -= SEG1;
    if (i < SEG2) { pack_qkv_w(q2w, k2w, v2w, wqkv2, i); return; }
    i -= SEG2;
    if (i < SEG3) { pack_wt(p1w, wp1, Cn, Cn, i); return; }
    i -= SEG3;
    if (i < SEG4) { pack_wt(p2w, wp2, Cn, Cn, i); return; }
    i -= SEG4;
    if (i < SEG5) { pack_wt(f1w, wf1, FFn, Cn, i); return; }
    i -= SEG5;
    if (i < SEG6) { pack_wt(f2w, wf2, Cn, FFn, i); return; }
    i -= SEG6;
    if (i < SEG7) {
        const float* b = (i < Cn) ? q1b : (i < 2 * Cn) ? k1b : v1b;
        bqkv1[i] = b[i % Cn]; return;
    }
    i -= SEG7;
    if (i < SEG8) {
        const float* b = (i < Cn) ? q2b : (i < 2 * Cn) ? k2b : v2b;
        bqkv2[i] = b[i % Cn]; return;
    }
    i -= SEG8;
    {
        float s, c;
        sincosf((float)i, &s, &c);
        rope[i] = make_float2(c, s);
    }
}

// ---------------- mma / ldmatrix / async helpers ----------------
__device__ __forceinline__ void mma16(float* d, const unsigned* a, const unsigned* b) {
    asm("mma.sync.aligned.m16n8k16.row.col.f32.f16.f16.f32 "
        "{%0,%1,%2,%3},{%4,%5,%6,%7},{%8,%9},{%0,%1,%2,%3};"
        : "+f"(d[0]), "+f"(d[1]), "+f"(d[2]), "+f"(d[3])
        : "r"(a[0]), "r"(a[1]), "r"(a[2]), "r"(a[3]), "r"(b[0]), "r"(b[1]));
}
__device__ __forceinline__ void ldsm4(unsigned* r, unsigned addr) {
    asm volatile("ldmatrix.sync.aligned.m8n8.x4.shared.b16 {%0,%1,%2,%3}, [%4];"
        : "=r"(r[0]), "=r"(r[1]), "=r"(r[2]), "=r"(r[3]) : "r"(addr));
}
__device__ __forceinline__ unsigned h2u(float a, float b) {
    __half2 h = __floats2half2_rn(a, b);
    return *(unsigned*)&h;
}
__device__ __forceinline__ void cp_async16(void* smem_dst, const void* gsrc) {
    unsigned saddr = (unsigned)__cvta_generic_to_shared(smem_dst);
    asm volatile("cp.async.ca.shared.global [%0], [%1], 16;\n" :: "r"(saddr), "l"(gsrc));
}
#define CP_COMMIT() asm volatile("cp.async.commit_group;\n" ::: "memory")
#define CP_WAIT0()  asm volatile("cp.async.wait_group 0;\n" ::: "memory")

// ---------------- fp16 GEMM: 4-stage pair-iterated, ldsm4-paired B ----------------
// flags: 0 = fp16 out (no relu); 1 = relu + fp16 out; 2 = qkv scatter fp16 (+rope)
__global__ __launch_bounds__(256) void gemm_f16(
    const __half* __restrict__ A, const __half* __restrict__ Bm,
    const float* __restrict__ bias,
    __half* __restrict__ Cout16,
    int M, int N, int K, int flags,
    __half* __restrict__ oq, __half* __restrict__ ok, __half* __restrict__ ov,
    const float2* __restrict__ rope)
{
    __shared__ __align__(16) unsigned As[4][128 * SWS];
    __shared__ __align__(16) unsigned Bs[4][128 * SWS];

    const int tid = threadIdx.x;
    const int lane = tid & 31, warp = tid >> 5;
    const int warpM = warp >> 2, warpN = warp & 3;
    const int bm = blockIdx.y * 128, bn = blockIdx.x * 128;
    const int qq = lane & 3, gg = lane >> 2;

    const int sRow = tid >> 1;
    const int sOff = (tid & 1) * 8;
    const __half* Ap = A + (size_t)(bm + sRow) * K + (tid & 1) * 16;
    const __half* Bp = Bm + (size_t)(bn + sRow) * K + (tid & 1) * 16;

    const int arS = warpM * 64 + (lane & 7) + ((lane >> 3) & 1) * 8;
    const int acS = (lane >> 4) * 4;
    const int br4 = warpN * 32 + ((lane >> 4) << 3) + (lane & 7);
    const int bc4 = ((lane >> 3) & 1) * 4;

    unsigned aBase[4], bBase[4];
#pragma unroll
    for (int s = 0; s < 4; s++) {
        aBase[s] = (unsigned)__cvta_generic_to_shared(As[s]);
        bBase[s] = (unsigned)__cvta_generic_to_shared(Bs[s]);
    }

    float acc[4][4][4];
#pragma unroll
    for (int i = 0; i < 4; i++)
#pragma unroll
        for (int j = 0; j < 4; j++)
#pragma unroll
            for (int r = 0; r < 4; r++) acc[i][j][r] = 0.f;

    const int KT = K >> 5;

    {
        unsigned* as0 = As[0]; unsigned* bs0 = Bs[0];
        cp_async16(as0 + sRow * SWS + sOff,     Ap);
        cp_async16(as0 + sRow * SWS + sOff + 4, Ap + 8);
        cp_async16(bs0 + sRow * SWS + sOff,     Bp);
        cp_async16(bs0 + sRow * SWS + sOff + 4, Bp + 8);
        unsigned* as1 = As[1]; unsigned* bs1 = Bs[1];
        cp_async16(as1 + sRow * SWS + sOff,     Ap + 32);
        cp_async16(as1 + sRow * SWS + sOff + 4, Ap + 40);
        cp_async16(bs1 + sRow * SWS + sOff,     Bp + 32);
        cp_async16(bs1 + sRow * SWS + sOff + 4, Bp + 40);
    }
    CP_COMMIT();

    for (int kt2 = 0; kt2 < KT; kt2 += 2) {
        CP_WAIT0();
        __syncthreads();

        if (kt2 + 2 < KT) {
            int stA = (kt2 + 2) & 3, stB = (kt2 + 3) & 3;
            const __half* apA = Ap + (size_t)(kt2 + 2) * 32;
            const __half* bpA = Bp + (size_t)(kt2 + 2) * 32;
            unsigned* as = As[stA]; unsigned* bs = Bs[stA];
            cp_async16(as + sRow * SWS + sOff,     apA);
            cp_async16(as + sRow * SWS + sOff + 4, apA + 8);
            cp_async16(bs + sRow * SWS + sOff,     bpA);
            cp_async16(bs + sRow * SWS + sOff + 4, bpA + 8);
            unsigned* as2 = As[stB]; unsigned* bs2 = Bs[stB];
            cp_async16(as2 + sRow * SWS + sOff,     apA + 32);
            cp_async16(as2 + sRow * SWS + sOff + 4, apA + 40);
            cp_async16(bs2 + sRow * SWS + sOff,     bpA + 32);
            cp_async16(bs2 + sRow * SWS + sOff + 4, bpA + 40);
            CP_COMMIT();
        }

#pragma unroll
        for (int sub = 0; sub < 2; sub++) {
            const unsigned ab = aBase[(kt2 + sub) & 3];
            const unsigned bb = bBase[(kt2 + sub) & 3];
#pragma unroll
            for (int ko = 0; ko < 16; ko += 8) {
                unsigned af[4][4], bf4[2][4];
#pragma unroll
                for (int mi = 0; mi < 4; mi++)
                    ldsm4(af[mi], ab + (((mi * 16 + arS) * SWS + ko + acS) << 2));
#pragma unroll
                for (int np = 0; np < 2; np++)
                    ldsm4(bf4[np], bb + (((np * 16 + br4) * SWS + ko + bc4) << 2));
#pragma unroll
                for (int mi = 0; mi < 4; mi++)
#pragma unroll
                    for (int ni = 0; ni < 4; ni++)
                        mma16(acc[mi][ni], af[mi], &bf4[ni >> 1][(ni & 1) * 2]);
            }
        }
    }

    const float scale = 0.051031036307982884f;   // 1/sqrt(384)
#pragma unroll
    for (int mi = 0; mi < 4; mi++) {
        int row0 = bm + warpM * 64 + mi * 16 + gg;
        float sn[2], cs[2];
        if (flags == 2) {
            float2 rc0 = rope[row0 & 511];
            float2 rc1 = rope[(row0 + 8) & 511];
            cs[0] = rc0.x; sn[0] = rc0.y;
            cs[1] = rc1.x; sn[1] = rc1.y;
        }
#pragma unroll
        for (int ni = 0; ni < 4; ni++) {
            int col = bn + warpN * 32 + ni * 8 + qq * 2;
            float b0 = bias[col], b1 = bias[col + 1];
#pragma unroll
            for (int half = 0; half < 2; half++) {
                int row = row0 + half * 8;
                float xr = acc[mi][ni][half * 2 + 0] + b0;
                float xi = acc[mi][ni][half * 2 + 1] + b1;
                if (flags == 2) {
                    int mat = col / Cn;
                    if (mat < 2) {
                        float nr = cs[half] * xr - sn[half] * xi;
                        float ni2 = sn[half] * xr + cs[half] * xi;
                        xr = nr; xi = ni2;
                    }
                    int local = col - mat * Cn;
                    int h = local >> 6, d = local & 63;
                    int bbv = row >> 9, t = row & 511;
                    if (mat == 0) {
                        __half2 hv = __floats2half2_rn(xr * scale, xi * scale);
                        *(__half2*)(oq + ((size_t)(bbv * Hn + h) * Tn + t) * HDn + d) = hv;
                    } else if (mat == 1) {
                        __half2 hv = __floats2half2_rn(xr, xi);
                        *(__half2*)(ok + ((size_t)(bbv * Hn + h) * Tn + t) * HDn + d) = hv;
                    } else {
                        size_t vb = ((size_t)(bbv * Hn + h) * HDn + d) * Tn + t;
                        ov[vb]      = __float2half(xr);
                        ov[vb + Tn] = __float2half(xi);
                    }
                } else {
                    if (flags == 1) { xr = fmaxf(xr, 0.f); xi = fmaxf(xi, 0.f); }
                    __half2* p = (__half2*)(Cout16 + (size_t)row * N + col);
                    *p = __floats2half2_rn(xr, xi);
                }
            }
        }
    }
}

// ---------------- fp16 causal flash attention: 128q tile, 64-key stages, x4 loads -
__global__ __launch_bounds__(256) void attn_mma(
    const __half* __restrict__ q, const __half* __restrict__ k,
    const __half* __restrict__ v, __half* __restrict__ o)
{
    __shared__ __align__(16) unsigned sm[ATOT];

    const int bh = blockIdx.y;
    const int qt = gridDim.x - 1 - blockIdx.x;
    const int tid = threadIdx.x;
    const int warp = tid >> 5, lane = tid & 31;
    const int gg = lane >> 2, qq = lane & 3;
    const size_t base = (size_t)bh * Tn * HDn;
    const int q0 = qt * 128;
    const int ktiles = 2 * qt + 2;

    const int a4r = ((lane >> 4) << 3) + (lane & 7);
    const int a4c = ((lane >> 3) & 1) * 4;

    {
        unsigned* kd = sm + AK0;
        unsigned* vd = sm + AV0;
#pragma unroll
        for (int i = 0; i < 2; i++) {
            int idx = i * 256 + tid;
            int r = idx >> 3, seg = idx & 7;
            cp_async16(kd + r * ASTK + seg * 4, k + base + (size_t)r * 64 + seg * 8);
            cp_async16(vd + r * ASTV + seg * 4, v + base + (size_t)r * Tn + seg * 8);
        }
        CP_COMMIT();
    }

    unsigned qf[4][4];
    {
        const __half* q0p = q + base + (size_t)(q0 + warp * 16 + gg) * 64;
        const __half* q1p = q0p + 8 * 64;
#pragma unroll
        for (int ks = 0; ks < 4; ks++) {
            qf[ks][0] = *(const unsigned*)(q0p + ks * 16 + 2 * qq);
            qf[ks][1] = *(const unsigned*)(q1p + ks * 16 + 2 * qq);
            qf[ks][2] = *(const unsigned*)(q0p + ks * 16 + 2 * qq + 8);
            qf[ks][3] = *(const unsigned*)(q1p + ks * 16 + 2 * qq + 8);
        }
    }
    CP_WAIT0();
    __syncthreads();

    float oacc[8][4];
#pragma unroll
    for (int i = 0; i < 8; i++)
#pragma unroll
        for (int r = 0; r < 4; r++) oacc[i][r] = 0.f;
    float m0 = -INFINITY, m1 = -INFINITY, l0 = 0.f, l1 = 0.f;

    const int row0g = q0 + warp * 16 + gg;
    const int row1g = row0g + 8;

    for (int kt = 0; kt < ktiles; kt++) {
        const unsigned* Ks = sm + ((kt & 1) ? AK1 : AK0);
        const unsigned* Vs = sm + ((kt & 1) ? AV1 : AV0);

        if (kt + 1 < ktiles) {
            unsigned* kd = sm + (((kt + 1) & 1) ? AK1 : AK0);
            unsigned* vd = sm + (((kt + 1) & 1) ? AV1 : AV0);
            const int nb = (kt + 1) * 64;
#pragma unroll
            for (int i = 0; i < 2; i++) {
                int idx = i * 256 + tid;
                int r = idx >> 3, seg = idx & 7;
                cp_async16(kd + r * ASTK + seg * 4,
                           k + base + (size_t)(nb + r) * 64 + seg * 8);
                cp_async16(vd + r * ASTV + seg * 4,
                           v + base + (size_t)r * Tn + nb + seg * 8);
            }
            CP_COMMIT();
        }

        const unsigned vsBase = (unsigned)__cvta_generic_to_shared(Vs);

#pragma unroll
        for (int sub = 0; sub < 2; sub++) {
            const int kbase = kt * 64 + sub * 32;
            const unsigned ksBase = (unsigned)__cvta_generic_to_shared(Ks + sub * 32 * ASTK);
            const int vcol = sub * 16;

            float s[4][4];
#pragma unroll
            for (int nt = 0; nt < 4; nt++)
#pragma unroll
                for (int r = 0; r < 4; r++) s[nt][r] = 0.f;
#pragma unroll
            for (int ks = 0; ks < 4; ks++) {
                unsigned bk[2][4];
#pragma unroll
                for (int np = 0; np < 2; np++)
                    ldsm4(bk[np], ksBase + (((np * 16 + a4r) * ASTK + ks * 8 + a4c) << 2));
#pragma unroll
                for (int nt = 0; nt < 4; nt++)
                    mma16(s[nt], qf[ks], &bk[nt >> 1][(nt & 1) * 2]);
            }

            if (kt >= 2 * qt) {
#pragma unroll
                for (int nt = 0; nt < 4; nt++) {
                    int c0 = kbase + nt * 8 + 2 * qq;
                    if (c0 > row0g)     s[nt][0] = -1e30f;
                    if (c0 + 1 > row0g) s[nt][1] = -1e30f;
                    if (c0 > row1g)     s[nt][2] = -1e30f;
                    if (c0 + 1 > row1g) s[nt][3] = -1e30f;
                }
            }

            float rm0 = -1e30f, rm1 = -1e30f;
#pragma unroll
            for (int nt = 0; nt < 4; nt++) {
                rm0 = fmaxf(rm0, fmaxf(s[nt][0], s[nt][1]));
                rm1 = fmaxf(rm1, fmaxf(s[nt][2], s[nt][3]));
            }
            rm0 = fmaxf(rm0, __shfl_xor_sync(0xffffffffu, rm0, 1));
            rm0 = fmaxf(rm0, __shfl_xor_sync(0xffffffffu, rm0, 2));
            rm1 = fmaxf(rm1, __shfl_xor_sync(0xffffffffu, rm1, 1));
            rm1 = fmaxf(rm1, __shfl_xor_sync(0xffffffffu, rm1, 2));
            float nm0 = fmaxf(m0, rm0), nm1 = fmaxf(m1, rm1);
            float corr0 = __expf(m0 - nm0), corr1 = __expf(m1 - nm1);
            float rs0 = 0.f, rs1 = 0.f;
#pragma unroll
            for (int nt = 0; nt < 4; nt++) {
                s[nt][0] = __expf(s[nt][0] - nm0);
                s[nt][1] = __expf(s[nt][1] - nm0);
                s[nt][2] = __expf(s[nt][2] - nm1);
                s[nt][3] = __expf(s[nt][3] - nm1);
                rs0 += s[nt][0] + s[nt][1];
                rs1 += s[nt][2] + s[nt][3];
            }
            rs0 += __shfl_xor_sync(0xffffffffu, rs0, 1);
            rs0 += __shfl_xor_sync(0xffffffffu, rs0, 2);
            rs1 += __shfl_xor_sync(0xffffffffu, rs1, 1);
            rs1 += __shfl_xor_sync(0xffffffffu, rs1, 2);
            l0 = l0 * corr0 + rs0;
            l1 = l1 * corr1 + rs1;
            m0 = nm0; m1 = nm1;
#pragma unroll
            for (int nt = 0; nt < 8; nt++) {
                oacc[nt][0] *= corr0; oacc[nt][1] *= corr0;
                oacc[nt][2] *= corr1; oacc[nt][3] *= corr1;
            }

            unsigned pa[2][4];
            pa[0][0] = h2u(s[0][0], s[0][1]);
            pa[0][1] = h2u(s[0][2], s[0][3]);
            pa[0][2] = h2u(s[1][0], s[1][1]);
            pa[0][3] = h2u(s[1][2], s[1][3]);
            pa[1][0] = h2u(s[2][0], s[2][1]);
            pa[1][1] = h2u(s[2][2], s[2][3]);
            pa[1][2] = h2u(s[3][0], s[3][1]);
            pa[1][3] = h2u(s[3][2], s[3][3]);

#pragma unroll
            for (int ks = 0; ks < 2; ks++) {
                unsigned bv[4][4];
#pragma unroll
                for (int np = 0; np < 4; np++)
                    ldsm4(bv[np], vsBase + (((np * 16 + a4r) * ASTV + vcol + ks * 8 + a4c) << 2));
#pragma unroll
                for (int nt = 0; nt < 8; nt++)
                    mma16(oacc[nt], pa[ks], &bv[nt >> 1][(nt & 1) * 2]);
            }
        }

        if (kt + 1 < ktiles) {
            CP_WAIT0();
            __syncthreads();
        }
    }

    const float inv0 = 1.f / l0, inv1 = 1.f / l1;
    const int b = bh / Hn, h = bh % Hn;
    __half* p0 = o + ((size_t)(b * Tn + row0g)) * Cn + h * 64;
    __half* p1 = o + ((size_t)(b * Tn + row1g)) * Cn + h * 64;
#pragma unroll
    for (int nt = 0; nt < 8; nt++) {
        *(__half2*)(p0 + nt * 8 + 2 * qq) = __floats2half2_rn(oacc[nt][0] * inv0, oacc[nt][1] * inv0);
        *(__half2*)(p1 + nt * 8 + 2 * qq) = __floats2half2_rn(oacc[nt][2] * inv1, oacc[nt][3] * inv1);
    }
}

// ---------------- fused residual + LayerNorm: fp16 x & y, fp16/fp32 out -----------
__global__ __launch_bounds__(256) void ln_res_k(
    const __half* __restrict__ x, const __half* __restrict__ y,
    const float* __restrict__ g, const float* __restrict__ bb,
    float* __restrict__ out32, __half* __restrict__ out16)
{
    __shared__ float red[8];
    const int half = threadIdx.x >> 7;
    const int tid = threadIdx.x & 127;
    const int row = blockIdx.x * 2 + half;
    const size_t base = (size_t)row * Cn;
    float v0 = __half2float(x[base + tid])       + __half2float(y[base + tid]);
    float v1 = __half2float(x[base + tid + 128]) + __half2float(y[base + tid + 128]);
    float v2 = __half2float(x[base + tid + 256]) + __half2float(y[base + tid + 256]);

    float s = v0 + v1 + v2;
    for (int o = 16; o > 0; o >>= 1) s += __shfl_xor_sync(0xffffffffu, s, o);
    if ((tid & 31) == 0) red[half * 4 + (tid >> 5)] = s;
    __syncthreads();
    float mean = (red[half * 4] + red[half * 4 + 1] + red[half * 4 + 2] + red[half * 4 + 3]) * (1.f / Cn);
    __syncthreads();

    float d0 = v0 - mean, d1 = v1 - mean, d2 = v2 - mean;
    float sq = d0 * d0 + d1 * d1 + d2 * d2;
    for (int o = 16; o > 0; o >>= 1) sq += __shfl_xor_sync(0xffffffffu, sq, o);
    if ((tid & 31) == 0) red[half * 4 + (tid >> 5)] = sq;
    __syncthreads();
    float var = (red[half * 4] + red[half * 4 + 1] + red[half * 4 + 2] + red[half * 4 + 3]) * (1.f / Cn);
    float inv = rsqrtf(var + EPSn);

    float o0 = g[tid]       * d0 * inv + bb[tid];
    float o1 = g[tid + 128] * d1 * inv + bb[tid + 128];
    float o2 = g[tid + 256] * d2 * inv + bb[tid + 256];
    if (out32) {
        out32[base + tid]       = o0;
        out32[base + tid + 128] = o1;
        out32[base + tid + 256] = o2;
    }
    if (out16) {
        out16[base + tid]       = __float2half(o0);
        out16[base + tid + 128] = __float2half(o1);
        out16[base + tid + 256] = __float2half(o2);
    }
}

// ---------------- host orchestration ----------------
extern "C" void kernel_launch(void* const* d_in, const int* in_sizes, int n_in,
                              void* d_out, int out_size)
{
    (void)in_sizes; (void)n_in; (void)out_size;
    const float* x    = (const float*)d_in[0];
    const float* q1w  = (const float*)d_in[1];
    const float* q1b  = (const float*)d_in[2];
    const float* k1w  = (const float*)d_in[3];
    const float* k1b  = (const float*)d_in[4];
    const float* v1w  = (const float*)d_in[5];
    const float* v1b  = (const float*)d_in[6];
    const float* p1w  = (const float*)d_in[7];
    const float* p1b  = (const float*)d_in[8];
    const float* ln1g = (const float*)d_in[9];
    const float* ln1b = (const float*)d_in[10];
    const float* q2w  = (const float*)d_in[11];
    const float* q2b  = (const float*)d_in[12];
    const float* k2w  = (const float*)d_in[13];
    const float* k2b  = (const float*)d_in[14];
    const float* v2w  = (const float*)d_in[15];
    const float* v2b  = (const float*)d_in[16];
    const float* p2w  = (const float*)d_in[17];
    const float* p2b  = (const float*)d_in[18];
    const float* ln2g = (const float*)d_in[19];
    const float* ln2b = (const float*)d_in[20];
    const float* f1w  = (const float*)d_in[21];
    const float* f1b  = (const float*)d_in[22];
    const float* f2w  = (const float*)d_in[23];
    const float* f2b  = (const float*)d_in[24];
    const float* ln3g = (const float*)d_in[25];
    const float* ln3b = (const float*)d_in[26];
    float* out = (float*)d_out;

    __half *pwqkv1, *pwqkv2, *pwp1, *pwp2, *pwf1, *pwf2;
    __half *px16, *po16, *pr16, *ph16, *py16, *pq16, *pk16, *pv16t;
    float *pbqkv1, *pbqkv2;
    float2* prope;
    cudaGetSymbolAddress((void**)&pwqkv1, g_wqkv1);
    cudaGetSymbolAddress((void**)&pwqkv2, g_wqkv2);
    cudaGetSymbolAddress((void**)&pwp1, g_wp1);
    cudaGetSymbolAddress((void**)&pwp2, g_wp2);
    cudaGetSymbolAddress((void**)&pwf1, g_wf1t);
    cudaGetSymbolAddress((void**)&pwf2, g_wf2t);
    cudaGetSymbolAddress((void**)&px16, g_x16);
    cudaGetSymbolAddress((void**)&po16, g_o16);
    cudaGetSymbolAddress((void**)&pr16, g_r16);
    cudaGetSymbolAddress((void**)&ph16, g_h16);
    cudaGetSymbolAddress((void**)&py16, g_y16);
    cudaGetSymbolAddress((void**)&pq16, g_q16);
    cudaGetSymbolAddress((void**)&pk16, g_k16);
    cudaGetSymbolAddress((void**)&pv16t, g_v16t);
    cudaGetSymbolAddress((void**)&pbqkv1, g_bqkv1);
    cudaGetSymbolAddress((void**)&pbqkv2, g_bqkv2);
    cudaGetSymbolAddress((void**)&prope, g_rope);

    prep_all<<<(PTOT + 255) / 256, 256>>>(
        x, px16,
        q1w, k1w, v1w, pwqkv1,
        q2w, k2w, v2w, pwqkv2,
        p1w, pwp1, p2w, pwp2,
        f1w, pwf1, f2w, pwf2,
        q1b, k1b, v1b, pbqkv1,
        q2b, k2b, v2b, pbqkv2,
        prope);

    // ---- layer 1 ----
    gemm_f16<<<dim3(3 * Cn / 128, BTn / 128), 256>>>(
        px16, pwqkv1, pbqkv1, nullptr, BTn, 3 * Cn, Cn, 2, pq16, pk16, pv16t, prope);
    attn_mma<<<dim3(Tn / 128, Bn * Hn), 256>>>(pq16, pk16, pv16t, po16);
    gemm_f16<<<dim3(Cn / 128, BTn / 128), 256>>>(
        po16, pwp1, p1b, py16, BTn, Cn, Cn, 0, nullptr, nullptr, nullptr, prope);
    ln_res_k<<<BTn / 2, 256>>>(px16, py16, ln1g, ln1b, nullptr, pr16);

    // ---- layer 2 ----
    gemm_f16<<<dim3(3 * Cn / 128, BTn / 128), 256>>>(
        pr16, pwqkv2, pbqkv2, nullptr, BTn, 3 * Cn, Cn, 2, pq16, pk16, pv16t, prope);
    attn_mma<<<dim3(Tn / 128, Bn * Hn), 256>>>(pq16, pk16, pv16t, po16);
    gemm_f16<<<dim3(Cn / 128, BTn / 128), 256>>>(
        po16, pwp2, p2b, py16, BTn, Cn, Cn, 0, nullptr, nullptr, nullptr, prope);
    ln_res_k<<<BTn / 2, 256>>>(pr16, py16, ln2g, ln2b, nullptr, pr16);

    // ---- FF + final LN ----
    gemm_f16<<<dim3(FFn / 128, BTn / 128), 256>>>(
        pr16, pwf1, f1b, ph16, BTn, FFn, Cn, 1, nullptr, nullptr, nullptr, prope);
    gemm_f16<<<dim3(Cn / 128, BTn / 128), 256>>>(
        ph16, pwf2, f2b, py16, BTn, Cn, FFn, 0, nullptr, nullptr, nullptr, prope);
    ln_res_k<<<BTn / 2, 256>>>(pr16, py16, ln3g, ln3b, out, nullptr);
}

// round 17
// speedup vs baseline: 1.6309x; 1.0105x over previous
#include <cuda_runtime.h>
#include <cuda_fp16.h>
#include <math.h>

#define Bn 64
#define Tn 512
#define Cn 384
#define Hn 6
#define HDn 64
#define FFn 1536
#define BTn (Bn*Tn)
#define EPSn 1e-5f

#define SWS 20    // gemm smem row stride (u32 words)

// fp16 attention smem (u32 word strides), 64-key stages
#define ASTK 36
#define ASTV 36
#define AK0 0
#define AV0 (64*ASTK)
#define AK1 (2*64*ASTK)
#define AV1 (3*64*ASTK)
#define ATOT (4*64*ASTK)

// ---------------- scratch ----------------
__device__ __half g_wqkv1[3*Cn*Cn];
__device__ __half g_wqkv2[3*Cn*Cn];
__device__ __half g_wp1[Cn*Cn];
__device__ __half g_wp2[Cn*Cn];
__device__ __half g_wf1t[FFn*Cn];
__device__ __half g_wf2t[Cn*FFn];
__device__ float  g_bqkv1[3*Cn];
__device__ float  g_bqkv2[3*Cn];
__device__ float2 g_rope[Tn];
__device__ __half g_x16[(size_t)BTn*Cn];
__device__ __half g_o16[(size_t)BTn*Cn];
__device__ __half g_r16[(size_t)BTn*Cn];
__device__ __half g_h16[(size_t)BTn*FFn];
__device__ __half g_y16[(size_t)BTn*Cn];
__device__ __half g_q16[(size_t)Bn*Hn*Tn*HDn];
__device__ __half g_k16[(size_t)Bn*Hn*Tn*HDn];
__device__ __half g_v16t[(size_t)Bn*Hn*HDn*Tn];

// ---------------- fused prep ----------------
#define SEG0 (BTn*Cn)
#define SEG1 (3*Cn*Cn)
#define SEG2 (3*Cn*Cn)
#define SEG3 (Cn*Cn)
#define SEG4 (Cn*Cn)
#define SEG5 (FFn*Cn)
#define SEG6 (Cn*FFn)
#define SEG7 (3*Cn)
#define SEG8 (3*Cn)
#define SEG9 (Tn)
#define PTOT (SEG0+SEG1+SEG2+SEG3+SEG4+SEG5+SEG6+SEG7+SEG8+SEG9)

__device__ __forceinline__ void pack_qkv_w(const float* qw, const float* kw,
                                           const float* vw, __half* o, int i) {
    int n = i / Cn, k = i % Cn;
    int mat = n / Cn, local = n % Cn;
    int h = local >> 6, d = local & 63;
    const float* w = (mat == 0) ? qw : (mat == 1) ? kw : vw;
    o[i] = __float2half(w[((size_t)h * Cn + k) * HDn + d]);
}
__device__ __forceinline__ void pack_wt(const float* w, __half* o, int N, int K, int i) {
    int n = i / K, k = i % K;
    o[i] = __float2half(w[(size_t)k * N + n]);
}

__global__ void prep_all(
    const float* __restrict__ x, __half* __restrict__ x16,
    const float* __restrict__ q1w, const float* __restrict__ k1w, const float* __restrict__ v1w,
    __half* __restrict__ wqkv1,
    const float* __restrict__ q2w, const float* __restrict__ k2w, const float* __restrict__ v2w,
    __half* __restrict__ wqkv2,
    const float* __restrict__ p1w, __half* __restrict__ wp1,
    const float* __restrict__ p2w, __half* __restrict__ wp2,
    const float* __restrict__ f1w, __half* __restrict__ wf1,
    const float* __restrict__ f2w, __half* __restrict__ wf2,
    const float* __restrict__ q1b, const float* __restrict__ k1b, const float* __restrict__ v1b,
    float* __restrict__ bqkv1,
    const float* __restrict__ q2b, const float* __restrict__ k2b, const float* __restrict__ v2b,
    float* __restrict__ bqkv2,
    float2* __restrict__ rope)
{
    int i = blockIdx.x * blockDim.x + threadIdx.x;
    if (i >= PTOT) return;
    if (i < SEG0) { x16[i] = __float2half(x[i]); return; }
    i -= SEG0;
    if (i < SEG1) { pack_qkv_w(q1w, k1w, v1w, wqkv1, i); return; }
    i -= SEG1;
    if (i < SEG2) { pack_qkv_w(q2w, k2w, v2w, wqkv2, i); return; }
    i -= SEG2;
    if (i < SEG3) { pack_wt(p1w, wp1, Cn, Cn, i); return; }
    i -= SEG3;
    if (i < SEG4) { pack_wt(p2w, wp2, Cn, Cn, i); return; }
    i -= SEG4;
    if (i < SEG5) { pack_wt(f1w, wf1, FFn, Cn, i); return; }
    i -= SEG5;
    if (i < SEG6) { pack_wt(f2w, wf2, Cn, FFn, i); return; }
    i -= SEG6;
    if (i < SEG7) {
        const float* b = (i < Cn) ? q1b : (i < 2 * Cn) ? k1b : v1b;
        bqkv1[i] = b[i % Cn]; return;
    }
    i -= SEG7;
    if (i < SEG8) {
        const float* b = (i < Cn) ? q2b : (i < 2 * Cn) ? k2b : v2b;
        bqkv2[i] = b[i % Cn]; return;
    }
    i -= SEG8;
    {
        float s, c;
        sincosf((float)i, &s, &c);
        rope[i] = make_float2(c, s);
    }
}

// ---------------- mma / ldmatrix / async helpers ----------------
__device__ __forceinline__ void mma16(float* d, const unsigned* a, const unsigned* b) {
    asm("mma.sync.aligned.m16n8k16.row.col.f32.f16.f16.f32 "
        "{%0,%1,%2,%3},{%4,%5,%6,%7},{%8,%9},{%0,%1,%2,%3};"
        : "+f"(d[0]), "+f"(d[1]), "+f"(d[2]), "+f"(d[3])
        : "r"(a[0]), "r"(a[1]), "r"(a[2]), "r"(a[3]), "r"(b[0]), "r"(b[1]));
}
__device__ __forceinline__ void ldsm4(unsigned* r, unsigned addr) {
    asm volatile("ldmatrix.sync.aligned.m8n8.x4.shared.b16 {%0,%1,%2,%3}, [%4];"
        : "=r"(r[0]), "=r"(r[1]), "=r"(r[2]), "=r"(r[3]) : "r"(addr));
}
__device__ __forceinline__ unsigned h2u(float a, float b) {
    __half2 h = __floats2half2_rn(a, b);
    return *(unsigned*)&h;
}
__device__ __forceinline__ void cp_async16(void* smem_dst, const void* gsrc) {
    unsigned saddr = (unsigned)__cvta_generic_to_shared(smem_dst);
    asm volatile("cp.async.ca.shared.global [%0], [%1], 16;\n" :: "r"(saddr), "l"(gsrc));
}
#define CP_COMMIT() asm volatile("cp.async.commit_group;\n" ::: "memory")
#define CP_WAIT0()  asm volatile("cp.async.wait_group 0;\n" ::: "memory")

// ---------------- fp16 GEMM: 4-stage pair-iterated, ldsm4-paired B ----------------
// flags: 0 = fp16 out (no relu); 1 = relu + fp16 out; 2 = qkv scatter fp16 (+rope)
__global__ __launch_bounds__(256) void gemm_f16(
    const __half* __restrict__ A, const __half* __restrict__ Bm,
    const float* __restrict__ bias,
    __half* __restrict__ Cout16,
    int M, int N, int K, int flags,
    __half* __restrict__ oq, __half* __restrict__ ok, __half* __restrict__ ov,
    const float2* __restrict__ rope)
{
    __shared__ __align__(16) unsigned As[4][128 * SWS];
    __shared__ __align__(16) unsigned Bs[4][128 * SWS];

    const int tid = threadIdx.x;
    const int lane = tid & 31, warp = tid >> 5;
    const int warpM = warp >> 2, warpN = warp & 3;
    const int bm = blockIdx.y * 128, bn = blockIdx.x * 128;
    const int qq = lane & 3, gg = lane >> 2;

    const int sRow = tid >> 1;
    const int sOff = (tid & 1) * 8;
    const __half* Ap = A + (size_t)(bm + sRow) * K + (tid & 1) * 16;
    const __half* Bp = Bm + (size_t)(bn + sRow) * K + (tid & 1) * 16;

    const int arS = warpM * 64 + (lane & 7) + ((lane >> 3) & 1) * 8;
    const int acS = (lane >> 4) * 4;
    const int br4 = warpN * 32 + ((lane >> 4) << 3) + (lane & 7);
    const int bc4 = ((lane >> 3) & 1) * 4;

    unsigned aBase[4], bBase[4];
#pragma unroll
    for (int s = 0; s < 4; s++) {
        aBase[s] = (unsigned)__cvta_generic_to_shared(As[s]);
        bBase[s] = (unsigned)__cvta_generic_to_shared(Bs[s]);
    }

    float acc[4][4][4];
#pragma unroll
    for (int i = 0; i < 4; i++)
#pragma unroll
        for (int j = 0; j < 4; j++)
#pragma unroll
            for (int r = 0; r < 4; r++) acc[i][j][r] = 0.f;

    const int KT = K >> 5;

    {
        unsigned* as0 = As[0]; unsigned* bs0 = Bs[0];
        cp_async16(as0 + sRow * SWS + sOff,     Ap);
        cp_async16(as0 + sRow * SWS + sOff + 4, Ap + 8);
        cp_async16(bs0 + sRow * SWS + sOff,     Bp);
        cp_async16(bs0 + sRow * SWS + sOff + 4, Bp + 8);
        unsigned* as1 = As[1]; unsigned* bs1 = Bs[1];
        cp_async16(as1 + sRow * SWS + sOff,     Ap + 32);
        cp_async16(as1 + sRow * SWS + sOff + 4, Ap + 40);
        cp_async16(bs1 + sRow * SWS + sOff,     Bp + 32);
        cp_async16(bs1 + sRow * SWS + sOff + 4, Bp + 40);
    }
    CP_COMMIT();

    for (int kt2 = 0; kt2 < KT; kt2 += 2) {
        CP_WAIT0();
        __syncthreads();

        if (kt2 + 2 < KT) {
            int stA = (kt2 + 2) & 3, stB = (kt2 + 3) & 3;
            const __half* apA = Ap + (size_t)(kt2 + 2) * 32;
            const __half* bpA = Bp + (size_t)(kt2 + 2) * 32;
            unsigned* as = As[stA]; unsigned* bs = Bs[stA];
            cp_async16(as + sRow * SWS + sOff,     apA);
            cp_async16(as + sRow * SWS + sOff + 4, apA + 8);
            cp_async16(bs + sRow * SWS + sOff,     bpA);
            cp_async16(bs + sRow * SWS + sOff + 4, bpA + 8);
            unsigned* as2 = As[stB]; unsigned* bs2 = Bs[stB];
            cp_async16(as2 + sRow * SWS + sOff,     apA + 32);
            cp_async16(as2 + sRow * SWS + sOff + 4, apA + 40);
            cp_async16(bs2 + sRow * SWS + sOff,     bpA + 32);
            cp_async16(bs2 + sRow * SWS + sOff + 4, bpA + 40);
            CP_COMMIT();
        }

#pragma unroll
        for (int sub = 0; sub < 2; sub++) {
            const unsigned ab = aBase[(kt2 + sub) & 3];
            const unsigned bb = bBase[(kt2 + sub) & 3];
#pragma unroll
            for (int ko = 0; ko < 16; ko += 8) {
                unsigned af[4][4], bf4[2][4];
#pragma unroll
                for (int mi = 0; mi < 4; mi++)
                    ldsm4(af[mi], ab + (((mi * 16 + arS) * SWS + ko + acS) << 2));
#pragma unroll
                for (int np = 0; np < 2; np++)
                    ldsm4(bf4[np], bb + (((np * 16 + br4) * SWS + ko + bc4) << 2));
#pragma unroll
                for (int mi = 0; mi < 4; mi++)
#pragma unroll
                    for (int ni = 0; ni < 4; ni++)
                        mma16(acc[mi][ni], af[mi], &bf4[ni >> 1][(ni & 1) * 2]);
            }
        }
    }

    const float scale = 0.051031036307982884f;   // 1/sqrt(384)
#pragma unroll
    for (int mi = 0; mi < 4; mi++) {
        int row0 = bm + warpM * 64 + mi * 16 + gg;
        float sn[2], cs[2];
        if (flags == 2) {
            float2 rc0 = rope[row0 & 511];
            float2 rc1 = rope[(row0 + 8) & 511];
            cs[0] = rc0.x; sn[0] = rc0.y;
            cs[1] = rc1.x; sn[1] = rc1.y;
        }
#pragma unroll
        for (int ni = 0; ni < 4; ni++) {
            int col = bn + warpN * 32 + ni * 8 + qq * 2;
            float b0 = bias[col], b1 = bias[col + 1];
#pragma unroll
            for (int half = 0; half < 2; half++) {
                int row = row0 + half * 8;
                float xr = acc[mi][ni][half * 2 + 0] + b0;
                float xi = acc[mi][ni][half * 2 + 1] + b1;
                if (flags == 2) {
                    int mat = col / Cn;
                    if (mat < 2) {
                        float nr = cs[half] * xr - sn[half] * xi;
                        float ni2 = sn[half] * xr + cs[half] * xi;
                        xr = nr; xi = ni2;
                    }
                    int local = col - mat * Cn;
                    int h = local >> 6, d = local & 63;
                    int bbv = row >> 9, t = row & 511;
                    if (mat == 0) {
                        __half2 hv = __floats2half2_rn(xr * scale, xi * scale);
                        *(__half2*)(oq + ((size_t)(bbv * Hn + h) * Tn + t) * HDn + d) = hv;
                    } else if (mat == 1) {
                        __half2 hv = __floats2half2_rn(xr, xi);
                        *(__half2*)(ok + ((size_t)(bbv * Hn + h) * Tn + t) * HDn + d) = hv;
                    } else {
                        size_t vb = ((size_t)(bbv * Hn + h) * HDn + d) * Tn + t;
                        ov[vb]      = __float2half(xr);
                        ov[vb + Tn] = __float2half(xi);
                    }
                } else {
                    if (flags == 1) { xr = fmaxf(xr, 0.f); xi = fmaxf(xi, 0.f); }
                    __half2* p = (__half2*)(Cout16 + (size_t)row * N + col);
                    *p = __floats2half2_rn(xr, xi);
                }
            }
        }
    }
}

// ---------------- fp16 causal flash attention: 128q tile, single 64-key softmax ---
__global__ __launch_bounds__(256) void attn_mma(
    const __half* __restrict__ q, const __half* __restrict__ k,
    const __half* __restrict__ v, __half* __restrict__ o)
{
    __shared__ __align__(16) unsigned sm[ATOT];

    const int bh = blockIdx.y;
    const int qt = gridDim.x - 1 - blockIdx.x;
    const int tid = threadIdx.x;
    const int warp = tid >> 5, lane = tid & 31;
    const int gg = lane >> 2, qq = lane & 3;
    const size_t base = (size_t)bh * Tn * HDn;
    const int q0 = qt * 128;
    const int ktiles = 2 * qt + 2;

    const int a4r = ((lane >> 4) << 3) + (lane & 7);
    const int a4c = ((lane >> 3) & 1) * 4;

    {
        unsigned* kd = sm + AK0;
        unsigned* vd = sm + AV0;
#pragma unroll
        for (int i = 0; i < 2; i++) {
            int idx = i * 256 + tid;
            int r = idx >> 3, seg = idx & 7;
            cp_async16(kd + r * ASTK + seg * 4, k + base + (size_t)r * 64 + seg * 8);
            cp_async16(vd + r * ASTV + seg * 4, v + base + (size_t)r * Tn + seg * 8);
        }
        CP_COMMIT();
    }

    unsigned qf[4][4];
    {
        const __half* q0p = q + base + (size_t)(q0 + warp * 16 + gg) * 64;
        const __half* q1p = q0p + 8 * 64;
#pragma unroll
        for (int ks = 0; ks < 4; ks++) {
            qf[ks][0] = *(const unsigned*)(q0p + ks * 16 + 2 * qq);
            qf[ks][1] = *(const unsigned*)(q1p + ks * 16 + 2 * qq);
            qf[ks][2] = *(const unsigned*)(q0p + ks * 16 + 2 * qq + 8);
            qf[ks][3] = *(const unsigned*)(q1p + ks * 16 + 2 * qq + 8);
        }
    }
    CP_WAIT0();
    __syncthreads();

    float oacc[8][4];
#pragma unroll
    for (int i = 0; i < 8; i++)
#pragma unroll
        for (int r = 0; r < 4; r++) oacc[i][r] = 0.f;
    float m0 = -INFINITY, m1 = -INFINITY, l0 = 0.f, l1 = 0.f;

    const int row0g = q0 + warp * 16 + gg;
    const int row1g = row0g + 8;

    for (int kt = 0; kt < ktiles; kt++) {
        const unsigned* Ks = sm + ((kt & 1) ? AK1 : AK0);
        const unsigned* Vs = sm + ((kt & 1) ? AV1 : AV0);

        if (kt + 1 < ktiles) {
            unsigned* kd = sm + (((kt + 1) & 1) ? AK1 : AK0);
            unsigned* vd = sm + (((kt + 1) & 1) ? AV1 : AV0);
            const int nb = (kt + 1) * 64;
#pragma unroll
            for (int i = 0; i < 2; i++) {
                int idx = i * 256 + tid;
                int r = idx >> 3, seg = idx & 7;
                cp_async16(kd + r * ASTK + seg * 4,
                           k + base + (size_t)(nb + r) * 64 + seg * 8);
                cp_async16(vd + r * ASTV + seg * 4,
                           v + base + (size_t)r * Tn + nb + seg * 8);
            }
            CP_COMMIT();
        }

        const unsigned ksBase = (unsigned)__cvta_generic_to_shared(Ks);
        const unsigned vsBase = (unsigned)__cvta_generic_to_shared(Vs);
        const int kbase = kt * 64;

        // S = Q K^T over all 64 keys (8 n-tiles)
        float s[8][4];
#pragma unroll
        for (int nt = 0; nt < 8; nt++)
#pragma unroll
            for (int r = 0; r < 4; r++) s[nt][r] = 0.f;
#pragma unroll
        for (int ks = 0; ks < 4; ks++) {
            unsigned bk[4][4];
#pragma unroll
            for (int np = 0; np < 4; np++)
                ldsm4(bk[np], ksBase + (((np * 16 + a4r) * ASTK + ks * 8 + a4c) << 2));
#pragma unroll
            for (int nt = 0; nt < 8; nt++)
                mma16(s[nt], qf[ks], &bk[nt >> 1][(nt & 1) * 2]);
        }

        // causal mask (last two 64-key tiles overlap the diagonal)
        if (kt >= 2 * qt) {
#pragma unroll
            for (int nt = 0; nt < 8; nt++) {
                int c0 = kbase + nt * 8 + 2 * qq;
                if (c0 > row0g)     s[nt][0] = -1e30f;
                if (c0 + 1 > row0g) s[nt][1] = -1e30f;
                if (c0 > row1g)     s[nt][2] = -1e30f;
                if (c0 + 1 > row1g) s[nt][3] = -1e30f;
            }
        }

        // single online softmax over 64 keys
        float rm0 = -1e30f, rm1 = -1e30f;
#pragma unroll
        for (int nt = 0; nt < 8; nt++) {
            rm0 = fmaxf(rm0, fmaxf(s[nt][0], s[nt][1]));
            rm1 = fmaxf(rm1, fmaxf(s[nt][2], s[nt][3]));
        }
        rm0 = fmaxf(rm0, __shfl_xor_sync(0xffffffffu, rm0, 1));
        rm0 = fmaxf(rm0, __shfl_xor_sync(0xffffffffu, rm0, 2));
        rm1 = fmaxf(rm1, __shfl_xor_sync(0xffffffffu, rm1, 1));
        rm1 = fmaxf(rm1, __shfl_xor_sync(0xffffffffu, rm1, 2));
        float nm0 = fmaxf(m0, rm0), nm1 = fmaxf(m1, rm1);
        float corr0 = __expf(m0 - nm0), corr1 = __expf(m1 - nm1);
        float rs0 = 0.f, rs1 = 0.f;
#pragma unroll
        for (int nt = 0; nt < 8; nt++) {
            s[nt][0] = __expf(s[nt][0] - nm0);
            s[nt][1] = __expf(s[nt][1] - nm0);
            s[nt][2] = __expf(s[nt][2] - nm1);
            s[nt][3] = __expf(s[nt][3] - nm1);
            rs0 += s[nt][0] + s[nt][1];
            rs1 += s[nt][2] + s[nt][3];
        }
        rs0 += __shfl_xor_sync(0xffffffffu, rs0, 1);
        rs0 += __shfl_xor_sync(0xffffffffu, rs0, 2);
        rs1 += __shfl_xor_sync(0xffffffffu, rs1, 1);
        rs1 += __shfl_xor_sync(0xffffffffu, rs1, 2);
        l0 = l0 * corr0 + rs0;
        l1 = l1 * corr1 + rs1;
        m0 = nm0; m1 = nm1;
#pragma unroll
        for (int nt = 0; nt < 8; nt++) {
            oacc[nt][0] *= corr0; oacc[nt][1] *= corr0;
            oacc[nt][2] *= corr1; oacc[nt][3] *= corr1;
        }

        // P A-fragments for 64 keys: pa[ks] covers keys [ks*16, ks*16+16)
        unsigned pa[4][4];
#pragma unroll
        for (int ks = 0; ks < 4; ks++) {
            pa[ks][0] = h2u(s[2 * ks][0],     s[2 * ks][1]);
            pa[ks][1] = h2u(s[2 * ks][2],     s[2 * ks][3]);
            pa[ks][2] = h2u(s[2 * ks + 1][0], s[2 * ks + 1][1]);
            pa[ks][3] = h2u(s[2 * ks + 1][2], s[2 * ks + 1][3]);
        }

        // O += P V : 4 k16 steps over 64 keys, 8 n-tiles of 8 d
#pragma unroll
        for (int ks = 0; ks < 4; ks++) {
            unsigned bv[4][4];
#pragma unroll
            for (int np = 0; np < 4; np++)
                ldsm4(bv[np], vsBase + (((np * 16 + a4r) * ASTV + ks * 8 + a4c) << 2));
#pragma unroll
            for (int nt = 0; nt < 8; nt++)
                mma16(oacc[nt], pa[ks], &bv[nt >> 1][(nt & 1) * 2]);
        }

        if (kt + 1 < ktiles) {
            CP_WAIT0();
            __syncthreads();
        }
    }

    const float inv0 = 1.f / l0, inv1 = 1.f / l1;
    const int b = bh / Hn, h = bh % Hn;
    __half* p0 = o + ((size_t)(b * Tn + row0g)) * Cn + h * 64;
    __half* p1 = o + ((size_t)(b * Tn + row1g)) * Cn + h * 64;
#pragma unroll
    for (int nt = 0; nt < 8; nt++) {
        *(__half2*)(p0 + nt * 8 + 2 * qq) = __floats2half2_rn(oacc[nt][0] * inv0, oacc[nt][1] * inv0);
        *(__half2*)(p1 + nt * 8 + 2 * qq) = __floats2half2_rn(oacc[nt][2] * inv1, oacc[nt][3] * inv1);
    }
}

// ---------------- fused residual + LayerNorm: fp16 x & y, fp16/fp32 out -----------
__global__ __launch_bounds__(256) void ln_res_k(
    const __half* __restrict__ x, const __half* __restrict__ y,
    const float* __restrict__ g, const float* __restrict__ bb,
    float* __restrict__ out32, __half* __restrict__ out16)
{
    __shared__ float red[8];
    const int half = threadIdx.x >> 7;
    const int tid = threadIdx.x & 127;
    const int row = blockIdx.x * 2 + half;
    const size_t base = (size_t)row * Cn;
    float v0 = __half2float(x[base + tid])       + __half2float(y[base + tid]);
    float v1 = __half2float(x[base + tid + 128]) + __half2float(y[base + tid + 128]);
    float v2 = __half2float(x[base + tid + 256]) + __half2float(y[base + tid + 256]);

    float s = v0 + v1 + v2;
    for (int o = 16; o > 0; o >>= 1) s += __shfl_xor_sync(0xffffffffu, s, o);
    if ((tid & 31) == 0) red[half * 4 + (tid >> 5)] = s;
    __syncthreads();
    float mean = (red[half * 4] + red[half * 4 + 1] + red[half * 4 + 2] + red[half * 4 + 3]) * (1.f / Cn);
    __syncthreads();

    float d0 = v0 - mean, d1 = v1 - mean, d2 = v2 - mean;
    float sq = d0 * d0 + d1 * d1 + d2 * d2;
    for (int o = 16; o > 0; o >>= 1) sq += __shfl_xor_sync(0xffffffffu, sq, o);
    if ((tid & 31) == 0) red[half * 4 + (tid >> 5)] = sq;
    __syncthreads();
    float var = (red[half * 4] + red[half * 4 + 1] + red[half * 4 + 2] + red[half * 4 + 3]) * (1.f / Cn);
    float inv = rsqrtf(var + EPSn);

    float o0 = g[tid]       * d0 * inv + bb[tid];
    float o1 = g[tid + 128] * d1 * inv + bb[tid + 128];
    float o2 = g[tid + 256] * d2 * inv + bb[tid + 256];
    if (out32) {
        out32[base + tid]       = o0;
        out32[base + tid + 128] = o1;
        out32[base + tid + 256] = o2;
    }
    if (out16) {
        out16[base + tid]       = __float2half(o0);
        out16[base + tid + 128] = __float2half(o1);
        out16[base + tid + 256] = __float2half(o2);
    }
}

// ---------------- host orchestration ----------------
extern "C" void kernel_launch(void* const* d_in, const int* in_sizes, int n_in,
                              void* d_out, int out_size)
{
    (void)in_sizes; (void)n_in; (void)out_size;
    const float* x    = (const float*)d_in[0];
    const float* q1w  = (const float*)d_in[1];
    const float* q1b  = (const float*)d_in[2];
    const float* k1w  = (const float*)d_in[3];
    const float* k1b  = (const float*)d_in[4];
    const float* v1w  = (const float*)d_in[5];
    const float* v1b  = (const float*)d_in[6];
    const float* p1w  = (const float*)d_in[7];
    const float* p1b  = (const float*)d_in[8];
    const float* ln1g = (const float*)d_in[9];
    const float* ln1b = (const float*)d_in[10];
    const float* q2w  = (const float*)d_in[11];
    const float* q2b  = (const float*)d_in[12];
    const float* k2w  = (const float*)d_in[13];
    const float* k2b  = (const float*)d_in[14];
    const float* v2w  = (const float*)d_in[15];
    const float* v2b  = (const float*)d_in[16];
    const float* p2w  = (const float*)d_in[17];
    const float* p2b  = (const float*)d_in[18];
    const float* ln2g = (const float*)d_in[19];
    const float* ln2b = (const float*)d_in[20];
    const float* f1w  = (const float*)d_in[21];
    const float* f1b  = (const float*)d_in[22];
    const float* f2w  = (const float*)d_in[23];
    const float* f2b  = (const float*)d_in[24];
    const float* ln3g = (const float*)d_in[25];
    const float* ln3b = (const float*)d_in[26];
    float* out = (float*)d_out;

    __half *pwqkv1, *pwqkv2, *pwp1, *pwp2, *pwf1, *pwf2;
    __half *px16, *po16, *pr16, *ph16, *py16, *pq16, *pk16, *pv16t;
    float *pbqkv1, *pbqkv2;
    float2* prope;
    cudaGetSymbolAddress((void**)&pwqkv1, g_wqkv1);
    cudaGetSymbolAddress((void**)&pwqkv2, g_wqkv2);
    cudaGetSymbolAddress((void**)&pwp1, g_wp1);
    cudaGetSymbolAddress((void**)&pwp2, g_wp2);
    cudaGetSymbolAddress((void**)&pwf1, g_wf1t);
    cudaGetSymbolAddress((void**)&pwf2, g_wf2t);
    cudaGetSymbolAddress((void**)&px16, g_x16);
    cudaGetSymbolAddress((void**)&po16, g_o16);
    cudaGetSymbolAddress((void**)&pr16, g_r16);
    cudaGetSymbolAddress((void**)&ph16, g_h16);
    cudaGetSymbolAddress((void**)&py16, g_y16);
    cudaGetSymbolAddress((void**)&pq16, g_q16);
    cudaGetSymbolAddress((void**)&pk16, g_k16);
    cudaGetSymbolAddress((void**)&pv16t, g_v16t);
    cudaGetSymbolAddress((void**)&pbqkv1, g_bqkv1);
    cudaGetSymbolAddress((void**)&pbqkv2, g_bqkv2);
    cudaGetSymbolAddress((void**)&prope, g_rope);

    prep_all<<<(PTOT + 255) / 256, 256>>>(
        x, px16,
        q1w, k1w, v1w, pwqkv1,
        q2w, k2w, v2w, pwqkv2,
        p1w, pwp1, p2w, pwp2,
        f1w, pwf1, f2w, pwf2,
        q1b, k1b, v1b, pbqkv1,
        q2b, k2b, v2b, pbqkv2,
        prope);

    // ---- layer 1 ----
    gemm_f16<<<dim3(3 * Cn / 128, BTn / 128), 256>>>(
        px16, pwqkv1, pbqkv1, nullptr, BTn, 3 * Cn, Cn, 2, pq16, pk16, pv16t, prope);
    attn_mma<<<dim3(Tn / 128, Bn * Hn), 256>>>(pq16, pk16, pv16t, po16);
    gemm_f16<<<dim3(Cn / 128, BTn / 128), 256>>>(
        po16, pwp1, p1b, py16, BTn, Cn, Cn, 0, nullptr, nullptr, nullptr, prope);
    ln_res_k<<<BTn / 2, 256>>>(px16, py16, ln1g, ln1b, nullptr, pr16);

    // ---- layer 2 ----
    gemm_f16<<<dim3(3 * Cn / 128, BTn / 128), 256>>>(
        pr16, pwqkv2, pbqkv2, nullptr, BTn, 3 * Cn, Cn, 2, pq16, pk16, pv16t, prope);
    attn_mma<<<dim3(Tn / 128, Bn * Hn), 256>>>(pq16, pk16, pv16t, po16);
    gemm_f16<<<dim3(Cn / 128, BTn / 128), 256>>>(
        po16, pwp2, p2b, py16, BTn, Cn, Cn, 0, nullptr, nullptr, nullptr, prope);
    ln_res_k<<<BTn / 2, 256>>>(pr16, py16, ln2g, ln2b, nullptr, pr16);

    // ---- FF + final LN ----
    gemm_f16<<<dim3(FFn / 128, BTn / 128), 256>>>(
        pr16, pwf1, f1b, ph16, BTn, FFn, Cn, 1, nullptr, nullptr, nullptr, prope);
    gemm_f16<<<dim3(Cn / 128, BTn / 128), 256>>>(
        ph16, pwf2, f2b, py16, BTn, Cn, FFn, 0, nullptr, nullptr, nullptr, prope);
    ln_res_k<<<BTn / 2, 256>>>(pr16, py16, ln3g, ln3b, out, nullptr);
}